// round 11
// baseline (speedup 1.0000x reference)
#include <cuda_runtime.h>
#include <cuda_bf16.h>
#include <cstdint>
#include <math.h>

#define S_LEN 2048
#define HID   2048
#define NHEAD 16
#define HD    128

#define ATT_SCALE 0.08838834764831843f   // 128^-0.5

// Scratch (device globals — no allocation allowed)
__device__ float g_q[NHEAD * S_LEN * HD];
__device__ float g_k[NHEAD * S_LEN * HD];
__device__ float g_v[NHEAD * S_LEN * HD];
__device__ float g_attn[NHEAD * S_LEN * HD];

// ---------------------------------------------------------------------------
// Helpers
// ---------------------------------------------------------------------------
__device__ __forceinline__ float bf16rt(float x) {
    return __bfloat162float(__float2bfloat16_rn(x));
}
__device__ __forceinline__ unsigned packbf(float a, float b) {
    __nv_bfloat162 t = __floats2bfloat162_rn(a, b);
    return reinterpret_cast<unsigned&>(t);
}
__device__ __forceinline__ void ldsm4(const void* p, unsigned* r) {
    unsigned a = (unsigned)__cvta_generic_to_shared(p);
    asm volatile("ldmatrix.sync.aligned.m8n8.x4.shared.b16 {%0,%1,%2,%3}, [%4];"
                 : "=r"(r[0]), "=r"(r[1]), "=r"(r[2]), "=r"(r[3]) : "r"(a));
}
__device__ __forceinline__ void ldsm4t(const void* p, unsigned* r) {
    unsigned a = (unsigned)__cvta_generic_to_shared(p);
    asm volatile("ldmatrix.sync.aligned.m8n8.x4.trans.shared.b16 {%0,%1,%2,%3}, [%4];"
                 : "=r"(r[0]), "=r"(r[1]), "=r"(r[2]), "=r"(r[3]) : "r"(a));
}
__device__ __forceinline__ void mma_bf(float* c, const unsigned* a, const unsigned* b) {
    asm volatile("mma.sync.aligned.m16n8k16.row.col.f32.bf16.bf16.f32 "
                 "{%0,%1,%2,%3},{%4,%5,%6,%7},{%8,%9},{%0,%1,%2,%3};"
                 : "+f"(c[0]), "+f"(c[1]), "+f"(c[2]), "+f"(c[3])
                 : "r"(a[0]), "r"(a[1]), "r"(a[2]), "r"(a[3]),
                   "r"(b[0]), "r"(b[1]));
}
// Convert 2 float4 (8 fp32) -> hi/lo bf16x8 and store 16B each.
__device__ __forceinline__ void split_store_regs(void* hi, void* lo,
                                                 const float4& v0, const float4& v1) {
    float h0 = bf16rt(v0.x), h1 = bf16rt(v0.y), h2 = bf16rt(v0.z), h3 = bf16rt(v0.w);
    float h4 = bf16rt(v1.x), h5 = bf16rt(v1.y), h6 = bf16rt(v1.z), h7 = bf16rt(v1.w);
    uint4 hh = make_uint4(packbf(h0, h1), packbf(h2, h3), packbf(h4, h5), packbf(h6, h7));
    uint4 ll = make_uint4(packbf(v0.x - h0, v0.y - h1), packbf(v0.z - h2, v0.w - h3),
                          packbf(v1.x - h4, v1.y - h5), packbf(v1.z - h6, v1.w - h7));
    *(uint4*)hi = hh;
    *(uint4*)lo = ll;
}

// ===========================================================================
// Pipelined split-bf16 HMMA GEMM: C[128,128] = A[128,K] @ B[128,K]^T (+bias)
// 512 threads (16 warps, 4x4 grid of 32x32 warp tiles), BK=64 fp32,
// register-staged prefetch of the next chunk during the MMA phase.
// ===========================================================================
#define GK 64                            // K per chunk (fp32)
#define GNCH (HID / GK)                  // 32 chunks
#define GSTRIDE 72                       // smem row stride in bf16 (64 + 8 pad)

struct GemmSmem {
    __nv_bfloat16 Ah[128][GSTRIDE];
    __nv_bfloat16 Al[128][GSTRIDE];
    __nv_bfloat16 Bh[128][GSTRIDE];
    __nv_bfloat16 Bl[128][GSTRIDE];
};

// Per-iteration body shared by both GEMM kernels via macro (A/B row pointers differ).
#define GEMM_BODY(LOADA_EXPR, LOADB_EXPR)                                       \
    __shared__ GemmSmem smem;                                                   \
    const int tid  = threadIdx.x;                                               \
    const int lane = tid & 31;                                                  \
    const int warp = tid >> 5;                                                  \
    const int wy = warp >> 2;                                                   \
    const int wx = warp & 3;                                                    \
    const int a_row  = lane & 15;                                               \
    const int a_csel = (lane >> 4) << 3;                                        \
    const int b_row  = (lane & 7) + ((lane >> 4) & 1) * 8;                      \
    const int b_csel = ((lane >> 3) & 1) * 8;                                   \
    const int r0i = tid >> 3, c8i = (tid & 7) * 8;                              \
    const int r1i = (tid + 512) >> 3, c8i1 = c8i;                               \
    float4 pa[4], pb[4];                                                        \
    float acc[2][4][4];                                                         \
    _Pragma("unroll")                                                           \
    for (int mt = 0; mt < 2; mt++)                                              \
        _Pragma("unroll")                                                       \
        for (int nt = 0; nt < 4; nt++)                                          \
            _Pragma("unroll")                                                   \
            for (int e = 0; e < 4; e++) acc[mt][nt][e] = 0.f;                   \
    {   /* prefetch chunk 0 */                                                  \
        const int kt = 0;                                                       \
        { int row = r0i, c8 = c8i;                                              \
          pa[0] = LOADA_EXPR; pa[1] = *(&(LOADA_EXPR) + 1);                     \
          pb[0] = LOADB_EXPR; pb[1] = *(&(LOADB_EXPR) + 1); }                   \
        { int row = r1i, c8 = c8i1;                                             \
          pa[2] = LOADA_EXPR; pa[3] = *(&(LOADA_EXPR) + 1);                     \
          pb[2] = LOADB_EXPR; pb[3] = *(&(LOADB_EXPR) + 1); }                   \
    }                                                                           \
    for (int ch = 0; ch < GNCH; ch++) {                                         \
        __syncthreads();                                                        \
        split_store_regs(&smem.Ah[r0i][c8i], &smem.Al[r0i][c8i], pa[0], pa[1]); \
        split_store_regs(&smem.Ah[r1i][c8i1], &smem.Al[r1i][c8i1], pa[2], pa[3]);\
        split_store_regs(&smem.Bh[r0i][c8i], &smem.Bl[r0i][c8i], pb[0], pb[1]); \
        split_store_regs(&smem.Bh[r1i][c8i1], &smem.Bl[r1i][c8i1], pb[2], pb[3]);\
        __syncthreads();                                                        \
        if (ch + 1 < GNCH) {                                                    \
            const int kt = (ch + 1) * GK;                                       \
            { int row = r0i, c8 = c8i;                                          \
              pa[0] = LOADA_EXPR; pa[1] = *(&(LOADA_EXPR) + 1);                 \
              pb[0] = LOADB_EXPR; pb[1] = *(&(LOADB_EXPR) + 1); }               \
            { int row = r1i, c8 = c8i1;                                         \
              pa[2] = LOADA_EXPR; pa[3] = *(&(LOADA_EXPR) + 1);                 \
              pb[2] = LOADB_EXPR; pb[3] = *(&(LOADB_EXPR) + 1); }               \
        }                                                                       \
        _Pragma("unroll")                                                       \
        for (int k16 = 0; k16 < 4; k16++) {                                     \
            int k0 = k16 * 16;                                                  \
            unsigned ah[2][4], al[2][4];                                        \
            _Pragma("unroll")                                                   \
            for (int mt = 0; mt < 2; mt++) {                                    \
                ldsm4(&smem.Ah[wy * 32 + mt * 16 + a_row][k0 + a_csel], ah[mt]);\
                ldsm4(&smem.Al[wy * 32 + mt * 16 + a_row][k0 + a_csel], al[mt]);\
            }                                                                   \
            _Pragma("unroll")                                                   \
            for (int ntp = 0; ntp < 2; ntp++) {                                 \
                unsigned bh[4], bl[4];                                          \
                ldsm4(&smem.Bh[wx * 32 + ntp * 16 + b_row][k0 + b_csel], bh);   \
                ldsm4(&smem.Bl[wx * 32 + ntp * 16 + b_row][k0 + b_csel], bl);   \
                _Pragma("unroll")                                               \
                for (int mt = 0; mt < 2; mt++) {                                \
                    mma_bf(acc[mt][2 * ntp],     ah[mt], bh);                   \
                    mma_bf(acc[mt][2 * ntp],     ah[mt], bl);                   \
                    mma_bf(acc[mt][2 * ntp],     al[mt], bh);                   \
                    mma_bf(acc[mt][2 * ntp + 1], ah[mt], bh + 2);               \
                    mma_bf(acc[mt][2 * ntp + 1], ah[mt], bl + 2);               \
                    mma_bf(acc[mt][2 * ntp + 1], al[mt], bh + 2);               \
                }                                                               \
            }                                                                   \
        }                                                                       \
    }

// ---------------------------------------------------------------------------
// QKV projection
// ---------------------------------------------------------------------------
__global__ __launch_bounds__(512, 1) void qkv_gemm_kernel(
    const float* __restrict__ X,
    const float* __restrict__ qw, const float* __restrict__ qb,
    const float* __restrict__ kw, const float* __restrict__ kb,
    const float* __restrict__ vw, const float* __restrict__ vb)
{
    const int z = blockIdx.z;
    const float* __restrict__ W    = (z == 0) ? qw : (z == 1) ? kw : vw;
    const float* __restrict__ bias = (z == 0) ? qb : (z == 1) ? kb : vb;
    float* dst = (z == 0) ? g_q : (z == 1) ? g_k : g_v;

    const int mbase = blockIdx.x * 128;
    const int head  = blockIdx.y;
    const int nbase = head * 128;

    GEMM_BODY((*(const float4*)&X[(size_t)(mbase + row) * HID + kt + c8]),
              (*(const float4*)&W[(size_t)(nbase + row) * HID + kt + c8]))

    const int g = lane >> 2;
    const int t = lane & 3;
    float* dbase = dst + (size_t)head * S_LEN * HD;
#pragma unroll
    for (int mt = 0; mt < 2; mt++) {
#pragma unroll
        for (int nt = 0; nt < 4; nt++) {
            int row = mbase + wy * 32 + mt * 16 + g;
            int col = wx * 32 + nt * 8 + 2 * t;
            float b0 = bias[nbase + col], b1 = bias[nbase + col + 1];
            *(float2*)&dbase[(size_t)row * HD + col] =
                make_float2(acc[mt][nt][0] + b0, acc[mt][nt][1] + b1);
            *(float2*)&dbase[(size_t)(row + 8) * HD + col] =
                make_float2(acc[mt][nt][2] + b0, acc[mt][nt][3] + b1);
        }
    }
}

// ---------------------------------------------------------------------------
// Output projection (A gathered from (head, s, d) layout)
// ---------------------------------------------------------------------------
__global__ __launch_bounds__(512, 1) void out_gemm_kernel(
    const float* __restrict__ ow, const float* __restrict__ ob,
    float* __restrict__ out)
{
    const int mbase = blockIdx.x * 128;
    const int nbase = blockIdx.y * 128;

    GEMM_BODY((*(const float4*)&g_attn[(size_t)(kt >> 7) * (S_LEN * HD) +
                                       (size_t)(mbase + row) * HD + (kt & 127) + c8]),
              (*(const float4*)&ow[(size_t)(nbase + row) * HID + kt + c8]))

    const int g = lane >> 2;
    const int t = lane & 3;
#pragma unroll
    for (int mt = 0; mt < 2; mt++) {
#pragma unroll
        for (int nt = 0; nt < 4; nt++) {
            int row = mbase + wy * 32 + mt * 16 + g;
            int col = wx * 32 + nt * 8 + 2 * t;
            float b0 = ob[nbase + col], b1 = ob[nbase + col + 1];
            *(float2*)&out[(size_t)row * HID + nbase + col] =
                make_float2(acc[mt][nt][0] + b0, acc[mt][nt][1] + b1);
            *(float2*)&out[(size_t)(row + 8) * HID + nbase + col] =
                make_float2(acc[mt][nt][2] + b0, acc[mt][nt][3] + b1);
        }
    }
}

// ===========================================================================
// Attention with split-bf16 MMA (unchanged from passing round-6 kernel).
// ===========================================================================
template<int MODE>   // 0 full, 1 keep j<=i, 2 keep j>i
__device__ __forceinline__ void softmax_update(
    float (&s)[16][4], float (&o)[16][4], float* m, float* l,
    int row0g, int kt, int lane)
{
    const int t = lane & 3;
    float bm0 = -INFINITY, bm1 = -INFINITY;
#pragma unroll
    for (int nt = 0; nt < 16; nt++) {
#pragma unroll
        for (int e = 0; e < 2; e++) {
            int j = kt + nt * 8 + 2 * t + e;
            float v0 = s[nt][e], v1 = s[nt][2 + e];
            if (MODE == 1) { if (j > row0g)      v0 = -INFINITY;
                             if (j > row0g + 8)  v1 = -INFINITY; }
            if (MODE == 2) { if (j <= row0g)     v0 = -INFINITY;
                             if (j <= row0g + 8) v1 = -INFINITY; }
            s[nt][e] = v0; s[nt][2 + e] = v1;
            bm0 = fmaxf(bm0, v0); bm1 = fmaxf(bm1, v1);
        }
    }
    bm0 = fmaxf(bm0, __shfl_xor_sync(0xffffffffu, bm0, 1));
    bm0 = fmaxf(bm0, __shfl_xor_sync(0xffffffffu, bm0, 2));
    bm1 = fmaxf(bm1, __shfl_xor_sync(0xffffffffu, bm1, 1));
    bm1 = fmaxf(bm1, __shfl_xor_sync(0xffffffffu, bm1, 2));
    float mn0 = fmaxf(m[0], bm0), mn1 = fmaxf(m[1], bm1);
    float f0 = __expf(m[0] - mn0), f1 = __expf(m[1] - mn1);
    float rs0 = 0.f, rs1 = 0.f;
#pragma unroll
    for (int nt = 0; nt < 16; nt++) {
#pragma unroll
        for (int e = 0; e < 2; e++) {
            float p0 = __expf(s[nt][e]     - mn0);
            float p1 = __expf(s[nt][2 + e] - mn1);
            s[nt][e] = p0; s[nt][2 + e] = p1;
            rs0 += p0; rs1 += p1;
        }
    }
    rs0 += __shfl_xor_sync(0xffffffffu, rs0, 1);
    rs0 += __shfl_xor_sync(0xffffffffu, rs0, 2);
    rs1 += __shfl_xor_sync(0xffffffffu, rs1, 1);
    rs1 += __shfl_xor_sync(0xffffffffu, rs1, 2);
    l[0] = l[0] * f0 + rs0; m[0] = mn0;
    l[1] = l[1] * f1 + rs1; m[1] = mn1;
#pragma unroll
    for (int nt = 0; nt < 16; nt++) {
        o[nt][0] *= f0; o[nt][1] *= f0;
        o[nt][2] *= f1; o[nt][3] *= f1;
    }
}

#define Q_HI_OFF 0
#define Q_LO_OFF 34816
#define KV_HI_OFF 69632
#define KV_LO_OFF 104448
#define PS_OFF    139264
#define ATT_SMEM  (139264 + 128 * 132 * 4)   // 206848

__global__ __launch_bounds__(256, 1) void attn_kernel()
{
    extern __shared__ char sm[];
    __nv_bfloat16 (*Qh)[136]  = (__nv_bfloat16(*)[136])(sm + Q_HI_OFF);
    __nv_bfloat16 (*Ql)[136]  = (__nv_bfloat16(*)[136])(sm + Q_LO_OFF);
    __nv_bfloat16 (*KVh)[136] = (__nv_bfloat16(*)[136])(sm + KV_HI_OFF);
    __nv_bfloat16 (*KVl)[136] = (__nv_bfloat16(*)[136])(sm + KV_LO_OFF);
    float* Ps = (float*)(sm + PS_OFF);       // raw S scratch, then oM snapshot

    const int h  = blockIdx.y;
    const int qt = blockIdx.x;
    const int qbase = qt * 128;
    const int tid  = threadIdx.x;
    const int lane = tid & 31;
    const int warp = tid >> 5;
    const int m0 = warp * 16;
    const int g = lane >> 2;
    const int t = lane & 3;

    const float* __restrict__ Qg = g_q + (size_t)h * S_LEN * HD;
    const float* __restrict__ Kg = g_k + (size_t)h * S_LEN * HD;
    const float* __restrict__ Vg = g_v + (size_t)h * S_LEN * HD;

    const int a_row  = lane & 15;
    const int a_csel = (lane >> 4) << 3;
    const int b_row  = (lane & 7) + ((lane >> 3) & 1) * 8;
    const int b_csel = ((lane >> 4) & 1) * 8;
    const int k_row  = (lane & 7) + ((lane >> 4) & 1) * 8;
    const int k_csel = ((lane >> 3) & 1) * 8;

#pragma unroll
    for (int i = 0; i < 16; i++) {
        int j = tid + i * 256;
        int row = j >> 5, c4 = (j & 31) << 2;
        float4 v = *(const float4*)&Qg[(size_t)(qbase + row) * HD + c4];
        v.x *= ATT_SCALE; v.y *= ATT_SCALE; v.z *= ATT_SCALE; v.w *= ATT_SCALE;
        float h0 = bf16rt(v.x), h1 = bf16rt(v.y), h2 = bf16rt(v.z), h3 = bf16rt(v.w);
        *(__nv_bfloat162*)&Qh[row][c4]     = __floats2bfloat162_rn(h0, h1);
        *(__nv_bfloat162*)&Qh[row][c4 + 2] = __floats2bfloat162_rn(h2, h3);
        *(__nv_bfloat162*)&Ql[row][c4]     = __floats2bfloat162_rn(v.x - h0, v.y - h1);
        *(__nv_bfloat162*)&Ql[row][c4 + 2] = __floats2bfloat162_rn(v.z - h2, v.w - h3);
    }

    float sacc[16][4], oacc[16][4];
    float m[2] = {-INFINITY, -INFINITY}, l[2] = {0.f, 0.f};
    float mM[2], lM[2];
#pragma unroll
    for (int nt = 0; nt < 16; nt++)
#pragma unroll
        for (int e = 0; e < 4; e++) oacc[nt][e] = 0.f;

    const int row0g = qbase + m0 + g;

    auto fill_kv = [&](const float* __restrict__ src, int kt) {
#pragma unroll
        for (int i = 0; i < 16; i++) {
            int j = tid + i * 256;
            int row = j >> 5, c4 = (j & 31) << 2;
            float4 v = *(const float4*)&src[(size_t)(kt + row) * HD + c4];
            float h0 = bf16rt(v.x), h1 = bf16rt(v.y), h2 = bf16rt(v.z), h3 = bf16rt(v.w);
            *(__nv_bfloat162*)&KVh[row][c4]     = __floats2bfloat162_rn(h0, h1);
            *(__nv_bfloat162*)&KVh[row][c4 + 2] = __floats2bfloat162_rn(h2, h3);
            *(__nv_bfloat162*)&KVl[row][c4]     = __floats2bfloat162_rn(v.x - h0, v.y - h1);
            *(__nv_bfloat162*)&KVl[row][c4 + 2] = __floats2bfloat162_rn(v.z - h2, v.w - h3);
        }
    };

    auto pv_accum = [&]() {
#pragma unroll
        for (int kc = 0; kc < 8; kc++) {
            unsigned ph[4], pl[4];
            float* s0 = sacc[2 * kc];
            float* s1 = sacc[2 * kc + 1];
            float h00 = bf16rt(s0[0]), h01 = bf16rt(s0[1]);
            float h02 = bf16rt(s0[2]), h03 = bf16rt(s0[3]);
            float h10 = bf16rt(s1[0]), h11 = bf16rt(s1[1]);
            float h12 = bf16rt(s1[2]), h13 = bf16rt(s1[3]);
            ph[0] = packbf(h00, h01); ph[1] = packbf(h02, h03);
            ph[2] = packbf(h10, h11); ph[3] = packbf(h12, h13);
            pl[0] = packbf(s0[0] - h00, s0[1] - h01);
            pl[1] = packbf(s0[2] - h02, s0[3] - h03);
            pl[2] = packbf(s1[0] - h10, s1[1] - h11);
            pl[3] = packbf(s1[2] - h12, s1[3] - h13);
#pragma unroll
            for (int dp = 0; dp < 8; dp++) {
                int d0 = dp * 16;
                unsigned vh[4], vl[4];
                ldsm4t(&KVh[kc * 16 + b_row][d0 + b_csel], vh);
                ldsm4t(&KVl[kc * 16 + b_row][d0 + b_csel], vl);
                mma_bf(oacc[2 * dp],     ph, vh);
                mma_bf(oacc[2 * dp],     ph, vl);
                mma_bf(oacc[2 * dp],     pl, vh);
                mma_bf(oacc[2 * dp + 1], ph, vh + 2);
                mma_bf(oacc[2 * dp + 1], ph, vl + 2);
                mma_bf(oacc[2 * dp + 1], pl, vh + 2);
            }
        }
    };

    for (int kt = 0; kt < S_LEN; kt += 128) {
        __syncthreads();
        fill_kv(Kg, kt);
        __syncthreads();

#pragma unroll
        for (int nt = 0; nt < 16; nt++)
#pragma unroll
            for (int e = 0; e < 4; e++) sacc[nt][e] = 0.f;
#pragma unroll
        for (int kc = 0; kc < 8; kc++) {
            int k0 = kc * 16;
            unsigned qh[4], ql[4];
            ldsm4(&Qh[m0 + a_row][k0 + a_csel], qh);
            ldsm4(&Ql[m0 + a_row][k0 + a_csel], ql);
#pragma unroll
            for (int ntp = 0; ntp < 8; ntp++) {
                unsigned kh[4], kl[4];
                ldsm4(&KVh[ntp * 16 + k_row][k0 + k_csel], kh);
                ldsm4(&KVl[ntp * 16 + k_row][k0 + k_csel], kl);
                mma_bf(sacc[2 * ntp],     qh, kh);
                mma_bf(sacc[2 * ntp],     qh, kl);
                mma_bf(sacc[2 * ntp],     ql, kh);
                mma_bf(sacc[2 * ntp + 1], qh, kh + 2);
                mma_bf(sacc[2 * ntp + 1], qh, kl + 2);
                mma_bf(sacc[2 * ntp + 1], ql, kh + 2);
            }
        }

        const bool diag = ((kt >> 7) == qt);
        if (diag) {
#pragma unroll
            for (int nt = 0; nt < 16; nt++) {
                int c = nt * 8 + 2 * t;
                *(float2*)&Ps[(m0 + g) * 132 + c]     = make_float2(sacc[nt][0], sacc[nt][1]);
                *(float2*)&Ps[(m0 + 8 + g) * 132 + c] = make_float2(sacc[nt][2], sacc[nt][3]);
            }
        }

        __syncthreads();
        fill_kv(Vg, kt);
        __syncthreads();

        if (!diag) {
            softmax_update<0>(sacc, oacc, m, l, row0g, kt, lane);
            pv_accum();
        } else {
            softmax_update<1>(sacc, oacc, m, l, row0g, kt, lane);
            pv_accum();
            mM[0] = m[0]; lM[0] = l[0]; mM[1] = m[1]; lM[1] = l[1];
            float inv0 = 1.f / (l[0] + 1e-8f), inv1 = 1.f / (l[1] + 1e-8f);
#pragma unroll
            for (int nt = 0; nt < 16; nt++) {
                int c = nt * 8 + 2 * t;
                float2 r0 = *(float2*)&Ps[(m0 + g) * 132 + c];
                float2 r1 = *(float2*)&Ps[(m0 + 8 + g) * 132 + c];
                *(float2*)&Ps[(m0 + g) * 132 + c] =
                    make_float2(oacc[nt][0] * inv0, oacc[nt][1] * inv0);
                *(float2*)&Ps[(m0 + 8 + g) * 132 + c] =
                    make_float2(oacc[nt][2] * inv1, oacc[nt][3] * inv1);
                sacc[nt][0] = r0.x; sacc[nt][1] = r0.y;
                sacc[nt][2] = r1.x; sacc[nt][3] = r1.y;
            }
            softmax_update<2>(sacc, oacc, m, l, row0g, kt, lane);
            pv_accum();
        }
    }

    float a0 = __expf(mM[0] - m[0]), a1 = __expf(mM[1] - m[1]);
    float invU0 = 1.f / (l[0] + 1e-8f), invU1 = 1.f / (l[1] + 1e-8f);
    float den0 = 1.f / (a0 * lM[0] + 3.f * l[0] + 1e-8f);
    float den1 = 1.f / (a1 * lM[1] + 3.f * l[1] + 1e-8f);
    float* Og = g_attn + (size_t)h * S_LEN * HD;
#pragma unroll
    for (int nt = 0; nt < 16; nt++) {
        int c = nt * 8 + 2 * t;
        float2 om0 = *(float2*)&Ps[(m0 + g) * 132 + c];
        float2 om1 = *(float2*)&Ps[(m0 + 8 + g) * 132 + c];
        float2 r0, r1;
        r0.x = (a0 * om0.x + 3.f * oacc[nt][0] * invU0) * den0;
        r0.y = (a0 * om0.y + 3.f * oacc[nt][1] * invU0) * den0;
        r1.x = (a1 * om1.x + 3.f * oacc[nt][2] * invU1) * den1;
        r1.y = (a1 * om1.y + 3.f * oacc[nt][3] * invU1) * den1;
        *(float2*)&Og[(size_t)(qbase + m0 + g) * HD + c]     = r0;
        *(float2*)&Og[(size_t)(qbase + m0 + 8 + g) * HD + c] = r1;
    }
}

extern "C" void kernel_launch(void* const* d_in, const int* in_sizes, int n_in,
                              void* d_out, int out_size)
{
    const float* X  = (const float*)d_in[0];
    const float* qw = (const float*)d_in[1];
    const float* qb = (const float*)d_in[2];
    const float* kw = (const float*)d_in[3];
    const float* kb = (const float*)d_in[4];
    const float* vw = (const float*)d_in[5];
    const float* vb = (const float*)d_in[6];
    const float* ow = (const float*)d_in[7];
    const float* ob = (const float*)d_in[8];
    float* out = (float*)d_out;

    cudaFuncSetAttribute(attn_kernel,
                         cudaFuncAttributeMaxDynamicSharedMemorySize, ATT_SMEM);

    qkv_gemm_kernel<<<dim3(16, 16, 3), 512>>>(X, qw, qb, kw, kb, vw, vb);
    attn_kernel<<<dim3(16, 16), 256, ATT_SMEM>>>();
    out_gemm_kernel<<<dim3(16, 16), 512>>>(ow, ob, out);
}

// round 12
// speedup vs baseline: 1.0146x; 1.0146x over previous
#include <cuda_runtime.h>
#include <cuda_bf16.h>
#include <cstdint>
#include <math.h>

#define S_LEN 2048
#define HID   2048
#define NHEAD 16
#define HD    128

#define ATT_SCALE 0.08838834764831843f   // 128^-0.5

// Scratch (device globals — no allocation allowed)
__device__ float g_q[NHEAD * S_LEN * HD];
__device__ float g_k[NHEAD * S_LEN * HD];
__device__ float g_v[NHEAD * S_LEN * HD];
__device__ float g_attn[NHEAD * S_LEN * HD];

// ---------------------------------------------------------------------------
// Helpers
// ---------------------------------------------------------------------------
__device__ __forceinline__ float bf16rt(float x) {
    return __bfloat162float(__float2bfloat16_rn(x));
}
__device__ __forceinline__ unsigned packbf(float a, float b) {
    __nv_bfloat162 t = __floats2bfloat162_rn(a, b);
    return reinterpret_cast<unsigned&>(t);
}
__device__ __forceinline__ void ldsm4(const void* p, unsigned* r) {
    unsigned a = (unsigned)__cvta_generic_to_shared(p);
    asm volatile("ldmatrix.sync.aligned.m8n8.x4.shared.b16 {%0,%1,%2,%3}, [%4];"
                 : "=r"(r[0]), "=r"(r[1]), "=r"(r[2]), "=r"(r[3]) : "r"(a));
}
__device__ __forceinline__ void ldsm4t(const void* p, unsigned* r) {
    unsigned a = (unsigned)__cvta_generic_to_shared(p);
    asm volatile("ldmatrix.sync.aligned.m8n8.x4.trans.shared.b16 {%0,%1,%2,%3}, [%4];"
                 : "=r"(r[0]), "=r"(r[1]), "=r"(r[2]), "=r"(r[3]) : "r"(a));
}
__device__ __forceinline__ void mma_bf(float* c, const unsigned* a, const unsigned* b) {
    asm volatile("mma.sync.aligned.m16n8k16.row.col.f32.bf16.bf16.f32 "
                 "{%0,%1,%2,%3},{%4,%5,%6,%7},{%8,%9},{%0,%1,%2,%3};"
                 : "+f"(c[0]), "+f"(c[1]), "+f"(c[2]), "+f"(c[3])
                 : "r"(a[0]), "r"(a[1]), "r"(a[2]), "r"(a[3]),
                   "r"(b[0]), "r"(b[1]));
}
// Convert 2 float4 (8 fp32) -> hi/lo bf16x8 and store 16B each.
__device__ __forceinline__ void split_store8(void* hi, void* lo,
                                             const float4& v0, const float4& v1) {
    float h0 = bf16rt(v0.x), h1 = bf16rt(v0.y), h2 = bf16rt(v0.z), h3 = bf16rt(v0.w);
    float h4 = bf16rt(v1.x), h5 = bf16rt(v1.y), h6 = bf16rt(v1.z), h7 = bf16rt(v1.w);
    uint4 hh = make_uint4(packbf(h0, h1), packbf(h2, h3), packbf(h4, h5), packbf(h6, h7));
    uint4 ll = make_uint4(packbf(v0.x - h0, v0.y - h1), packbf(v0.z - h2, v0.w - h3),
                          packbf(v1.x - h4, v1.y - h5), packbf(v1.z - h6, v1.w - h7));
    *(uint4*)hi = hh;
    *(uint4*)lo = ll;
}
__device__ __forceinline__ void cp16(unsigned smem_addr, const void* gptr) {
    asm volatile("cp.async.ca.shared.global [%0], [%1], 16;"
                 :: "r"(smem_addr), "l"(gptr) : "memory");
}
#define CP_COMMIT() asm volatile("cp.async.commit_group;" ::: "memory")
#define CP_WAIT1()  asm volatile("cp.async.wait_group 1;" ::: "memory")

// ===========================================================================
// cp.async-pipelined split-bf16 HMMA GEMM (R6 shape: 256 thr, 8 warps,
// warp tile 64x32, BK=32). fp32 staging double-buffered in smem via LDGSTS;
// short convert phase feeds bf16 hi/lo buffers; 2 CTAs/SM overlap phases.
//
// Dynamic smem layout (bytes):
//   Ah 0, Al 10240, Bh 20480, Bl 30720   (bf16 [128][40])
//   stageA 40960 (2 x 16384 fp32), stageB 73728 (2 x 16384)
// ===========================================================================
#define GS_AH  0
#define GS_AL  10240
#define GS_BH  20480
#define GS_BL  30720
#define GS_STA 40960
#define GS_STB 73728
#define GSMEM_TOTAL 106496

// ---------------------------------------------------------------------------
// QKV projection
// ---------------------------------------------------------------------------
__global__ __launch_bounds__(256, 2) void qkv_gemm_kernel(
    const float* __restrict__ X,
    const float* __restrict__ qw, const float* __restrict__ qb,
    const float* __restrict__ kw, const float* __restrict__ kb,
    const float* __restrict__ vw, const float* __restrict__ vb)
{
    extern __shared__ char smem[];
    __nv_bfloat16 (*Ah)[40] = (__nv_bfloat16(*)[40])(smem + GS_AH);
    __nv_bfloat16 (*Al)[40] = (__nv_bfloat16(*)[40])(smem + GS_AL);
    __nv_bfloat16 (*Bh)[40] = (__nv_bfloat16(*)[40])(smem + GS_BH);
    __nv_bfloat16 (*Bl)[40] = (__nv_bfloat16(*)[40])(smem + GS_BL);
    const unsigned sbase = (unsigned)__cvta_generic_to_shared(smem);

    const int z = blockIdx.z;
    const float* __restrict__ W    = (z == 0) ? qw : (z == 1) ? kw : vw;
    const float* __restrict__ bias = (z == 0) ? qb : (z == 1) ? kb : vb;
    float* dst = (z == 0) ? g_q : (z == 1) ? g_k : g_v;

    const int mbase = blockIdx.x * 128;
    const int head  = blockIdx.y;
    const int nbase = head * 128;
    const int tid  = threadIdx.x;
    const int lane = tid & 31;
    const int warp = tid >> 5;
    const int wy = warp >> 2;        // 0..1
    const int wx = warp & 3;         // 0..3

    const int a_row  = lane & 15;
    const int a_csel = (lane >> 4) << 3;
    const int b_row  = (lane & 7) + ((lane >> 4) & 1) * 8;
    const int b_csel = ((lane >> 3) & 1) * 8;

    const float* Abase = X + (size_t)mbase * HID;
    const float* Bbase = W + (size_t)nbase * HID;

    auto issue_chunk = [&](int kt, int stg) {
#pragma unroll
        for (int i = 0; i < 4; i++) {
            int s = tid + i * 256;
            int row = s >> 3, c4 = (s & 7) * 4;
            cp16(sbase + GS_STA + stg * 16384 + s * 16,
                 Abase + (size_t)row * HID + kt + c4);
            cp16(sbase + GS_STB + stg * 16384 + s * 16,
                 Bbase + (size_t)row * HID + kt + c4);
        }
    };
    auto convert_stage = [&](int stg) {
        const float4* sa4 = (const float4*)(smem + GS_STA + stg * 16384);
        const float4* sb4 = (const float4*)(smem + GS_STB + stg * 16384);
#pragma unroll
        for (int p = 0; p < 2; p++) {
            int s0 = 2 * (tid + p * 256);
            int row = s0 >> 3, c8 = (s0 & 7) * 4;
            float4 a0 = sa4[s0], a1 = sa4[s0 + 1];
            split_store8(&Ah[row][c8], &Al[row][c8], a0, a1);
            float4 b0 = sb4[s0], b1 = sb4[s0 + 1];
            split_store8(&Bh[row][c8], &Bl[row][c8], b0, b1);
        }
    };

    float acc[4][4][4];
#pragma unroll
    for (int mt = 0; mt < 4; mt++)
#pragma unroll
        for (int nt = 0; nt < 4; nt++)
#pragma unroll
            for (int e = 0; e < 4; e++) acc[mt][nt][e] = 0.f;

    issue_chunk(0, 0);
    CP_COMMIT();

    for (int ch = 0; ch < HID / 32; ch++) {
        const int cur = ch & 1;
        if (ch + 1 < HID / 32) issue_chunk((ch + 1) * 32, cur ^ 1);
        CP_COMMIT();
        CP_WAIT1();
        __syncthreads();
        convert_stage(cur);
        __syncthreads();

#pragma unroll
        for (int c3 = 0; c3 < 3; c3++) {
            const __nv_bfloat16 (*Asrc)[40] = (c3 == 2) ? Al : Ah;
            const __nv_bfloat16 (*Bsrc)[40] = (c3 == 1) ? Bl : Bh;
#pragma unroll
            for (int k16 = 0; k16 < 2; k16++) {
                int k0 = k16 * 16;
                unsigned a[4][4];
#pragma unroll
                for (int mt = 0; mt < 4; mt++)
                    ldsm4(&Asrc[wy * 64 + mt * 16 + a_row][k0 + a_csel], a[mt]);
#pragma unroll
                for (int ntp = 0; ntp < 2; ntp++) {
                    unsigned bb[4];
                    ldsm4(&Bsrc[wx * 32 + ntp * 16 + b_row][k0 + b_csel], bb);
#pragma unroll
                    for (int mt = 0; mt < 4; mt++) {
                        mma_bf(acc[mt][2 * ntp],     a[mt], bb);
                        mma_bf(acc[mt][2 * ntp + 1], a[mt], bb + 2);
                    }
                }
            }
        }
    }

    const int g = lane >> 2;
    const int t = lane & 3;
    float* dbase = dst + (size_t)head * S_LEN * HD;
#pragma unroll
    for (int mt = 0; mt < 4; mt++) {
#pragma unroll
        for (int nt = 0; nt < 4; nt++) {
            int row = mbase + wy * 64 + mt * 16 + g;
            int col = wx * 32 + nt * 8 + 2 * t;
            float b0 = bias[nbase + col], b1 = bias[nbase + col + 1];
            *(float2*)&dbase[(size_t)row * HD + col] =
                make_float2(acc[mt][nt][0] + b0, acc[mt][nt][1] + b1);
            *(float2*)&dbase[(size_t)(row + 8) * HD + col] =
                make_float2(acc[mt][nt][2] + b0, acc[mt][nt][3] + b1);
        }
    }
}

// ---------------------------------------------------------------------------
// Output projection (A gathered from (head, s, d) layout)
// ---------------------------------------------------------------------------
__global__ __launch_bounds__(256, 2) void out_gemm_kernel(
    const float* __restrict__ ow, const float* __restrict__ ob,
    float* __restrict__ out)
{
    extern __shared__ char smem[];
    __nv_bfloat16 (*Ah)[40] = (__nv_bfloat16(*)[40])(smem + GS_AH);
    __nv_bfloat16 (*Al)[40] = (__nv_bfloat16(*)[40])(smem + GS_AL);
    __nv_bfloat16 (*Bh)[40] = (__nv_bfloat16(*)[40])(smem + GS_BH);
    __nv_bfloat16 (*Bl)[40] = (__nv_bfloat16(*)[40])(smem + GS_BL);
    const unsigned sbase = (unsigned)__cvta_generic_to_shared(smem);

    const int mbase = blockIdx.x * 128;
    const int nbase = blockIdx.y * 128;
    const int tid  = threadIdx.x;
    const int lane = tid & 31;
    const int warp = tid >> 5;
    const int wy = warp >> 2;
    const int wx = warp & 3;

    const int a_row  = lane & 15;
    const int a_csel = (lane >> 4) << 3;
    const int b_row  = (lane & 7) + ((lane >> 4) & 1) * 8;
    const int b_csel = ((lane >> 3) & 1) * 8;

    auto issue_chunk = [&](int kt, int stg) {
        const float* abase = g_attn + (size_t)(kt >> 7) * (S_LEN * HD) + (kt & 127);
#pragma unroll
        for (int i = 0; i < 4; i++) {
            int s = tid + i * 256;
            int row = s >> 3, c4 = (s & 7) * 4;
            cp16(sbase + GS_STA + stg * 16384 + s * 16,
                 abase + (size_t)(mbase + row) * HD + c4);
            cp16(sbase + GS_STB + stg * 16384 + s * 16,
                 ow + (size_t)(nbase + row) * HID + kt + c4);
        }
    };
    auto convert_stage = [&](int stg) {
        const float4* sa4 = (const float4*)(smem + GS_STA + stg * 16384);
        const float4* sb4 = (const float4*)(smem + GS_STB + stg * 16384);
#pragma unroll
        for (int p = 0; p < 2; p++) {
            int s0 = 2 * (tid + p * 256);
            int row = s0 >> 3, c8 = (s0 & 7) * 4;
            float4 a0 = sa4[s0], a1 = sa4[s0 + 1];
            split_store8(&Ah[row][c8], &Al[row][c8], a0, a1);
            float4 b0 = sb4[s0], b1 = sb4[s0 + 1];
            split_store8(&Bh[row][c8], &Bl[row][c8], b0, b1);
        }
    };

    float acc[4][4][4];
#pragma unroll
    for (int mt = 0; mt < 4; mt++)
#pragma unroll
        for (int nt = 0; nt < 4; nt++)
#pragma unroll
            for (int e = 0; e < 4; e++) acc[mt][nt][e] = 0.f;

    issue_chunk(0, 0);
    CP_COMMIT();

    for (int ch = 0; ch < HID / 32; ch++) {
        const int cur = ch & 1;
        if (ch + 1 < HID / 32) issue_chunk((ch + 1) * 32, cur ^ 1);
        CP_COMMIT();
        CP_WAIT1();
        __syncthreads();
        convert_stage(cur);
        __syncthreads();

#pragma unroll
        for (int c3 = 0; c3 < 3; c3++) {
            const __nv_bfloat16 (*Asrc)[40] = (c3 == 2) ? Al : Ah;
            const __nv_bfloat16 (*Bsrc)[40] = (c3 == 1) ? Bl : Bh;
#pragma unroll
            for (int k16 = 0; k16 < 2; k16++) {
                int k0 = k16 * 16;
                unsigned a[4][4];
#pragma unroll
                for (int mt = 0; mt < 4; mt++)
                    ldsm4(&Asrc[wy * 64 + mt * 16 + a_row][k0 + a_csel], a[mt]);
#pragma unroll
                for (int ntp = 0; ntp < 2; ntp++) {
                    unsigned bb[4];
                    ldsm4(&Bsrc[wx * 32 + ntp * 16 + b_row][k0 + b_csel], bb);
#pragma unroll
                    for (int mt = 0; mt < 4; mt++) {
                        mma_bf(acc[mt][2 * ntp],     a[mt], bb);
                        mma_bf(acc[mt][2 * ntp + 1], a[mt], bb + 2);
                    }
                }
            }
        }
    }

    const int g = lane >> 2;
    const int t = lane & 3;
#pragma unroll
    for (int mt = 0; mt < 4; mt++) {
#pragma unroll
        for (int nt = 0; nt < 4; nt++) {
            int row = mbase + wy * 64 + mt * 16 + g;
            int col = wx * 32 + nt * 8 + 2 * t;
            float b0 = ob[nbase + col], b1 = ob[nbase + col + 1];
            *(float2*)&out[(size_t)row * HID + nbase + col] =
                make_float2(acc[mt][nt][0] + b0, acc[mt][nt][1] + b1);
            *(float2*)&out[(size_t)(row + 8) * HID + nbase + col] =
                make_float2(acc[mt][nt][2] + b0, acc[mt][nt][3] + b1);
        }
    }
}

// ===========================================================================
// Attention with split-bf16 MMA (unchanged from passing round-6 kernel).
// ===========================================================================
template<int MODE>   // 0 full, 1 keep j<=i, 2 keep j>i
__device__ __forceinline__ void softmax_update(
    float (&s)[16][4], float (&o)[16][4], float* m, float* l,
    int row0g, int kt, int lane)
{
    const int t = lane & 3;
    float bm0 = -INFINITY, bm1 = -INFINITY;
#pragma unroll
    for (int nt = 0; nt < 16; nt++) {
#pragma unroll
        for (int e = 0; e < 2; e++) {
            int j = kt + nt * 8 + 2 * t + e;
            float v0 = s[nt][e], v1 = s[nt][2 + e];
            if (MODE == 1) { if (j > row0g)      v0 = -INFINITY;
                             if (j > row0g + 8)  v1 = -INFINITY; }
            if (MODE == 2) { if (j <= row0g)     v0 = -INFINITY;
                             if (j <= row0g + 8) v1 = -INFINITY; }
            s[nt][e] = v0; s[nt][2 + e] = v1;
            bm0 = fmaxf(bm0, v0); bm1 = fmaxf(bm1, v1);
        }
    }
    bm0 = fmaxf(bm0, __shfl_xor_sync(0xffffffffu, bm0, 1));
    bm0 = fmaxf(bm0, __shfl_xor_sync(0xffffffffu, bm0, 2));
    bm1 = fmaxf(bm1, __shfl_xor_sync(0xffffffffu, bm1, 1));
    bm1 = fmaxf(bm1, __shfl_xor_sync(0xffffffffu, bm1, 2));
    float mn0 = fmaxf(m[0], bm0), mn1 = fmaxf(m[1], bm1);
    float f0 = __expf(m[0] - mn0), f1 = __expf(m[1] - mn1);
    float rs0 = 0.f, rs1 = 0.f;
#pragma unroll
    for (int nt = 0; nt < 16; nt++) {
#pragma unroll
        for (int e = 0; e < 2; e++) {
            float p0 = __expf(s[nt][e]     - mn0);
            float p1 = __expf(s[nt][2 + e] - mn1);
            s[nt][e] = p0; s[nt][2 + e] = p1;
            rs0 += p0; rs1 += p1;
        }
    }
    rs0 += __shfl_xor_sync(0xffffffffu, rs0, 1);
    rs0 += __shfl_xor_sync(0xffffffffu, rs0, 2);
    rs1 += __shfl_xor_sync(0xffffffffu, rs1, 1);
    rs1 += __shfl_xor_sync(0xffffffffu, rs1, 2);
    l[0] = l[0] * f0 + rs0; m[0] = mn0;
    l[1] = l[1] * f1 + rs1; m[1] = mn1;
#pragma unroll
    for (int nt = 0; nt < 16; nt++) {
        o[nt][0] *= f0; o[nt][1] *= f0;
        o[nt][2] *= f1; o[nt][3] *= f1;
    }
}

#define Q_HI_OFF 0
#define Q_LO_OFF 34816
#define KV_HI_OFF 69632
#define KV_LO_OFF 104448
#define PS_OFF    139264
#define ATT_SMEM  (139264 + 128 * 132 * 4)   // 206848

__global__ __launch_bounds__(256, 1) void attn_kernel()
{
    extern __shared__ char sm[];
    __nv_bfloat16 (*Qh)[136]  = (__nv_bfloat16(*)[136])(sm + Q_HI_OFF);
    __nv_bfloat16 (*Ql)[136]  = (__nv_bfloat16(*)[136])(sm + Q_LO_OFF);
    __nv_bfloat16 (*KVh)[136] = (__nv_bfloat16(*)[136])(sm + KV_HI_OFF);
    __nv_bfloat16 (*KVl)[136] = (__nv_bfloat16(*)[136])(sm + KV_LO_OFF);
    float* Ps = (float*)(sm + PS_OFF);       // raw S scratch, then oM snapshot

    const int h  = blockIdx.y;
    const int qt = blockIdx.x;
    const int qbase = qt * 128;
    const int tid  = threadIdx.x;
    const int lane = tid & 31;
    const int warp = tid >> 5;
    const int m0 = warp * 16;
    const int g = lane >> 2;
    const int t = lane & 3;

    const float* __restrict__ Qg = g_q + (size_t)h * S_LEN * HD;
    const float* __restrict__ Kg = g_k + (size_t)h * S_LEN * HD;
    const float* __restrict__ Vg = g_v + (size_t)h * S_LEN * HD;

    const int a_row  = lane & 15;
    const int a_csel = (lane >> 4) << 3;
    const int b_row  = (lane & 7) + ((lane >> 3) & 1) * 8;
    const int b_csel = ((lane >> 4) & 1) * 8;
    const int k_row  = (lane & 7) + ((lane >> 4) & 1) * 8;
    const int k_csel = ((lane >> 3) & 1) * 8;

#pragma unroll
    for (int i = 0; i < 16; i++) {
        int j = tid + i * 256;
        int row = j >> 5, c4 = (j & 31) << 2;
        float4 v = *(const float4*)&Qg[(size_t)(qbase + row) * HD + c4];
        v.x *= ATT_SCALE; v.y *= ATT_SCALE; v.z *= ATT_SCALE; v.w *= ATT_SCALE;
        float h0 = bf16rt(v.x), h1 = bf16rt(v.y), h2 = bf16rt(v.z), h3 = bf16rt(v.w);
        *(__nv_bfloat162*)&Qh[row][c4]     = __floats2bfloat162_rn(h0, h1);
        *(__nv_bfloat162*)&Qh[row][c4 + 2] = __floats2bfloat162_rn(h2, h3);
        *(__nv_bfloat162*)&Ql[row][c4]     = __floats2bfloat162_rn(v.x - h0, v.y - h1);
        *(__nv_bfloat162*)&Ql[row][c4 + 2] = __floats2bfloat162_rn(v.z - h2, v.w - h3);
    }

    float sacc[16][4], oacc[16][4];
    float m[2] = {-INFINITY, -INFINITY}, l[2] = {0.f, 0.f};
    float mM[2], lM[2];
#pragma unroll
    for (int nt = 0; nt < 16; nt++)
#pragma unroll
        for (int e = 0; e < 4; e++) oacc[nt][e] = 0.f;

    const int row0g = qbase + m0 + g;

    auto fill_kv = [&](const float* __restrict__ src, int kt) {
#pragma unroll
        for (int i = 0; i < 16; i++) {
            int j = tid + i * 256;
            int row = j >> 5, c4 = (j & 31) << 2;
            float4 v = *(const float4*)&src[(size_t)(kt + row) * HD + c4];
            float h0 = bf16rt(v.x), h1 = bf16rt(v.y), h2 = bf16rt(v.z), h3 = bf16rt(v.w);
            *(__nv_bfloat162*)&KVh[row][c4]     = __floats2bfloat162_rn(h0, h1);
            *(__nv_bfloat162*)&KVh[row][c4 + 2] = __floats2bfloat162_rn(h2, h3);
            *(__nv_bfloat162*)&KVl[row][c4]     = __floats2bfloat162_rn(v.x - h0, v.y - h1);
            *(__nv_bfloat162*)&KVl[row][c4 + 2] = __floats2bfloat162_rn(v.z - h2, v.w - h3);
        }
    };

    auto pv_accum = [&]() {
#pragma unroll
        for (int kc = 0; kc < 8; kc++) {
            unsigned ph[4], pl[4];
            float* s0 = sacc[2 * kc];
            float* s1 = sacc[2 * kc + 1];
            float h00 = bf16rt(s0[0]), h01 = bf16rt(s0[1]);
            float h02 = bf16rt(s0[2]), h03 = bf16rt(s0[3]);
            float h10 = bf16rt(s1[0]), h11 = bf16rt(s1[1]);
            float h12 = bf16rt(s1[2]), h13 = bf16rt(s1[3]);
            ph[0] = packbf(h00, h01); ph[1] = packbf(h02, h03);
            ph[2] = packbf(h10, h11); ph[3] = packbf(h12, h13);
            pl[0] = packbf(s0[0] - h00, s0[1] - h01);
            pl[1] = packbf(s0[2] - h02, s0[3] - h03);
            pl[2] = packbf(s1[0] - h10, s1[1] - h11);
            pl[3] = packbf(s1[2] - h12, s1[3] - h13);
#pragma unroll
            for (int dp = 0; dp < 8; dp++) {
                int d0 = dp * 16;
                unsigned vh[4], vl[4];
                ldsm4t(&KVh[kc * 16 + b_row][d0 + b_csel], vh);
                ldsm4t(&KVl[kc * 16 + b_row][d0 + b_csel], vl);
                mma_bf(oacc[2 * dp],     ph, vh);
                mma_bf(oacc[2 * dp],     ph, vl);
                mma_bf(oacc[2 * dp],     pl, vh);
                mma_bf(oacc[2 * dp + 1], ph, vh + 2);
                mma_bf(oacc[2 * dp + 1], ph, vl + 2);
                mma_bf(oacc[2 * dp + 1], pl, vh + 2);
            }
        }
    };

    for (int kt = 0; kt < S_LEN; kt += 128) {
        __syncthreads();
        fill_kv(Kg, kt);
        __syncthreads();

#pragma unroll
        for (int nt = 0; nt < 16; nt++)
#pragma unroll
            for (int e = 0; e < 4; e++) sacc[nt][e] = 0.f;
#pragma unroll
        for (int kc = 0; kc < 8; kc++) {
            int k0 = kc * 16;
            unsigned qh[4], ql[4];
            ldsm4(&Qh[m0 + a_row][k0 + a_csel], qh);
            ldsm4(&Ql[m0 + a_row][k0 + a_csel], ql);
#pragma unroll
            for (int ntp = 0; ntp < 8; ntp++) {
                unsigned kh[4], kl[4];
                ldsm4(&KVh[ntp * 16 + k_row][k0 + k_csel], kh);
                ldsm4(&KVl[ntp * 16 + k_row][k0 + k_csel], kl);
                mma_bf(sacc[2 * ntp],     qh, kh);
                mma_bf(sacc[2 * ntp],     qh, kl);
                mma_bf(sacc[2 * ntp],     ql, kh);
                mma_bf(sacc[2 * ntp + 1], qh, kh + 2);
                mma_bf(sacc[2 * ntp + 1], qh, kl + 2);
                mma_bf(sacc[2 * ntp + 1], ql, kh + 2);
            }
        }

        const bool diag = ((kt >> 7) == qt);
        if (diag) {
#pragma unroll
            for (int nt = 0; nt < 16; nt++) {
                int c = nt * 8 + 2 * t;
                *(float2*)&Ps[(m0 + g) * 132 + c]     = make_float2(sacc[nt][0], sacc[nt][1]);
                *(float2*)&Ps[(m0 + 8 + g) * 132 + c] = make_float2(sacc[nt][2], sacc[nt][3]);
            }
        }

        __syncthreads();
        fill_kv(Vg, kt);
        __syncthreads();

        if (!diag) {
            softmax_update<0>(sacc, oacc, m, l, row0g, kt, lane);
            pv_accum();
        } else {
            softmax_update<1>(sacc, oacc, m, l, row0g, kt, lane);
            pv_accum();
            mM[0] = m[0]; lM[0] = l[0]; mM[1] = m[1]; lM[1] = l[1];
            float inv0 = 1.f / (l[0] + 1e-8f), inv1 = 1.f / (l[1] + 1e-8f);
#pragma unroll
            for (int nt = 0; nt < 16; nt++) {
                int c = nt * 8 + 2 * t;
                float2 r0 = *(float2*)&Ps[(m0 + g) * 132 + c];
                float2 r1 = *(float2*)&Ps[(m0 + 8 + g) * 132 + c];
                *(float2*)&Ps[(m0 + g) * 132 + c] =
                    make_float2(oacc[nt][0] * inv0, oacc[nt][1] * inv0);
                *(float2*)&Ps[(m0 + 8 + g) * 132 + c] =
                    make_float2(oacc[nt][2] * inv1, oacc[nt][3] * inv1);
                sacc[nt][0] = r0.x; sacc[nt][1] = r0.y;
                sacc[nt][2] = r1.x; sacc[nt][3] = r1.y;
            }
            softmax_update<2>(sacc, oacc, m, l, row0g, kt, lane);
            pv_accum();
        }
    }

    float a0 = __expf(mM[0] - m[0]), a1 = __expf(mM[1] - m[1]);
    float invU0 = 1.f / (l[0] + 1e-8f), invU1 = 1.f / (l[1] + 1e-8f);
    float den0 = 1.f / (a0 * lM[0] + 3.f * l[0] + 1e-8f);
    float den1 = 1.f / (a1 * lM[1] + 3.f * l[1] + 1e-8f);
    float* Og = g_attn + (size_t)h * S_LEN * HD;
#pragma unroll
    for (int nt = 0; nt < 16; nt++) {
        int c = nt * 8 + 2 * t;
        float2 om0 = *(float2*)&Ps[(m0 + g) * 132 + c];
        float2 om1 = *(float2*)&Ps[(m0 + 8 + g) * 132 + c];
        float2 r0, r1;
        r0.x = (a0 * om0.x + 3.f * oacc[nt][0] * invU0) * den0;
        r0.y = (a0 * om0.y + 3.f * oacc[nt][1] * invU0) * den0;
        r1.x = (a1 * om1.x + 3.f * oacc[nt][2] * invU1) * den1;
        r1.y = (a1 * om1.y + 3.f * oacc[nt][3] * invU1) * den1;
        *(float2*)&Og[(size_t)(qbase + m0 + g) * HD + c]     = r0;
        *(float2*)&Og[(size_t)(qbase + m0 + 8 + g) * HD + c] = r1;
    }
}

extern "C" void kernel_launch(void* const* d_in, const int* in_sizes, int n_in,
                              void* d_out, int out_size)
{
    const float* X  = (const float*)d_in[0];
    const float* qw = (const float*)d_in[1];
    const float* qb = (const float*)d_in[2];
    const float* kw = (const float*)d_in[3];
    const float* kb = (const float*)d_in[4];
    const float* vw = (const float*)d_in[5];
    const float* vb = (const float*)d_in[6];
    const float* ow = (const float*)d_in[7];
    const float* ob = (const float*)d_in[8];
    float* out = (float*)d_out;

    cudaFuncSetAttribute(qkv_gemm_kernel,
                         cudaFuncAttributeMaxDynamicSharedMemorySize, GSMEM_TOTAL);
    cudaFuncSetAttribute(out_gemm_kernel,
                         cudaFuncAttributeMaxDynamicSharedMemorySize, GSMEM_TOTAL);
    cudaFuncSetAttribute(attn_kernel,
                         cudaFuncAttributeMaxDynamicSharedMemorySize, ATT_SMEM);

    qkv_gemm_kernel<<<dim3(16, 16, 3), 256, GSMEM_TOTAL>>>(X, qw, qb, kw, kb, vw, vb);
    attn_kernel<<<dim3(16, 16), 256, ATT_SMEM>>>();
    out_gemm_kernel<<<dim3(16, 16), 256, GSMEM_TOTAL>>>(ow, ob, out);
}

// round 14
// speedup vs baseline: 1.0838x; 1.0682x over previous
#include <cuda_runtime.h>
#include <cuda_bf16.h>
#include <cstdint>
#include <math.h>

#define S_LEN 2048
#define HID   2048
#define NHEAD 16
#define HD    128

#define ATT_SCALE 0.08838834764831843f   // 128^-0.5

__device__ float g_q[NHEAD * S_LEN * HD];
__device__ float g_k[NHEAD * S_LEN * HD];
__device__ float g_v[NHEAD * S_LEN * HD];
__device__ float g_attn[NHEAD * S_LEN * HD];

__device__ __forceinline__ float bf16rt(float x) {
    return __bfloat162float(__float2bfloat16_rn(x));
}
__device__ __forceinline__ unsigned packbf(float a, float b) {
    __nv_bfloat162 t = __floats2bfloat162_rn(a, b);
    return reinterpret_cast<unsigned&>(t);
}
__device__ __forceinline__ void ldsm4(const void* p, unsigned* r) {
    unsigned a = (unsigned)__cvta_generic_to_shared(p);
    asm volatile("ldmatrix.sync.aligned.m8n8.x4.shared.b16 {%0,%1,%2,%3}, [%4];"
                 : "=r"(r[0]), "=r"(r[1]), "=r"(r[2]), "=r"(r[3]) : "r"(a));
}
__device__ __forceinline__ void ldsm4t(const void* p, unsigned* r) {
    unsigned a = (unsigned)__cvta_generic_to_shared(p);
    asm volatile("ldmatrix.sync.aligned.m8n8.x4.trans.shared.b16 {%0,%1,%2,%3}, [%4];"
                 : "=r"(r[0]), "=r"(r[1]), "=r"(r[2]), "=r"(r[3]) : "r"(a));
}
__device__ __forceinline__ void mma_bf(float* c, const unsigned* a, const unsigned* b) {
    asm volatile("mma.sync.aligned.m16n8k16.row.col.f32.bf16.bf16.f32 "
                 "{%0,%1,%2,%3},{%4,%5,%6,%7},{%8,%9},{%0,%1,%2,%3};"
                 : "+f"(c[0]), "+f"(c[1]), "+f"(c[2]), "+f"(c[3])
                 : "r"(a[0]), "r"(a[1]), "r"(a[2]), "r"(a[3]),
                   "r"(b[0]), "r"(b[1]));
}

// Frag-reuse MMA phase: every fragment ldmatrix'd exactly once per k16,
// all 3 split-products issued from registers (12 ldsm / 48 MMA per k16).
#define GEMM_MMA_PHASE(ASH, ASL, BSH, BSL)                                     \
    _Pragma("unroll")                                                          \
    for (int k16 = 0; k16 < 2; k16++) {                                        \
        int k0 = k16 * 16;                                                     \
        unsigned bh[2][4], bl[2][4];                                           \
        _Pragma("unroll")                                                      \
        for (int ntp = 0; ntp < 2; ntp++) {                                    \
            ldsm4(&BSH[wx * 32 + ntp * 16 + b_row][k0 + b_csel], bh[ntp]);     \
            ldsm4(&BSL[wx * 32 + ntp * 16 + b_row][k0 + b_csel], bl[ntp]);     \
        }                                                                      \
        _Pragma("unroll")                                                      \
        for (int mt = 0; mt < 4; mt++) {                                       \
            unsigned ah[4], al[4];                                             \
            ldsm4(&ASH[wy * 64 + mt * 16 + a_row][k0 + a_csel], ah);           \
            ldsm4(&ASL[wy * 64 + mt * 16 + a_row][k0 + a_csel], al);           \
            mma_bf(acc[mt][0], ah, bh[0]);                                     \
            mma_bf(acc[mt][1], ah, bh[0] + 2);                                 \
            mma_bf(acc[mt][2], ah, bh[1]);                                     \
            mma_bf(acc[mt][3], ah, bh[1] + 2);                                 \
            mma_bf(acc[mt][0], ah, bl[0]);                                     \
            mma_bf(acc[mt][1], ah, bl[0] + 2);                                 \
            mma_bf(acc[mt][2], ah, bl[1]);                                     \
            mma_bf(acc[mt][3], ah, bl[1] + 2);                                 \
            mma_bf(acc[mt][0], al, bh[0]);                                     \
            mma_bf(acc[mt][1], al, bh[0] + 2);                                 \
            mma_bf(acc[mt][2], al, bh[1]);                                     \
            mma_bf(acc[mt][3], al, bh[1] + 2);                                 \
        }                                                                      \
    }

// ---------------------------------------------------------------------------
// QKV projection: Y = X @ W^T + b -> (head, s, d) layout.
// ---------------------------------------------------------------------------
__global__ __launch_bounds__(256, 2) void qkv_gemm_kernel(
    const float* __restrict__ X,
    const float* __restrict__ qw, const float* __restrict__ qb,
    const float* __restrict__ kw, const float* __restrict__ kb,
    const float* __restrict__ vw, const float* __restrict__ vb)
{
    __shared__ __nv_bfloat16 As_hi[128][40];
    __shared__ __nv_bfloat16 As_lo[128][40];
    __shared__ __nv_bfloat16 Bs_hi[128][40];
    __shared__ __nv_bfloat16 Bs_lo[128][40];

    const int z = blockIdx.z;
    const float* __restrict__ W    = (z == 0) ? qw : (z == 1) ? kw : vw;
    const float* __restrict__ bias = (z == 0) ? qb : (z == 1) ? kb : vb;
    float* dst = (z == 0) ? g_q : (z == 1) ? g_k : g_v;

    const int mbase = blockIdx.x * 128;
    const int head  = blockIdx.y;
    const int nbase = head * 128;
    const int tid  = threadIdx.x;
    const int lane = tid & 31;
    const int warp = tid >> 5;
    const int wy = warp >> 2;
    const int wx = warp & 3;

    const int a_row  = lane & 15;
    const int a_csel = (lane >> 4) << 3;
    const int b_row  = (lane & 7) + ((lane >> 4) & 1) * 8;
    const int b_csel = ((lane >> 3) & 1) * 8;

    float acc[4][4][4];
#pragma unroll
    for (int mt = 0; mt < 4; mt++)
#pragma unroll
        for (int nt = 0; nt < 4; nt++)
#pragma unroll
            for (int e = 0; e < 4; e++) acc[mt][nt][e] = 0.f;

    for (int kt = 0; kt < HID; kt += 32) {
        __syncthreads();
#pragma unroll
        for (int i = 0; i < 4; i++) {
            int j = tid + i * 256;
            int row = j >> 3, c4 = (j & 7) << 2;
            float4 v = *(const float4*)&X[(size_t)(mbase + row) * HID + kt + c4];
            float h0 = bf16rt(v.x), h1 = bf16rt(v.y), h2 = bf16rt(v.z), h3 = bf16rt(v.w);
            *(__nv_bfloat162*)&As_hi[row][c4]     = __floats2bfloat162_rn(h0, h1);
            *(__nv_bfloat162*)&As_hi[row][c4 + 2] = __floats2bfloat162_rn(h2, h3);
            *(__nv_bfloat162*)&As_lo[row][c4]     = __floats2bfloat162_rn(v.x - h0, v.y - h1);
            *(__nv_bfloat162*)&As_lo[row][c4 + 2] = __floats2bfloat162_rn(v.z - h2, v.w - h3);

            float4 w = *(const float4*)&W[(size_t)(nbase + row) * HID + kt + c4];
            float g0 = bf16rt(w.x), g1 = bf16rt(w.y), g2 = bf16rt(w.z), g3 = bf16rt(w.w);
            *(__nv_bfloat162*)&Bs_hi[row][c4]     = __floats2bfloat162_rn(g0, g1);
            *(__nv_bfloat162*)&Bs_hi[row][c4 + 2] = __floats2bfloat162_rn(g2, g3);
            *(__nv_bfloat162*)&Bs_lo[row][c4]     = __floats2bfloat162_rn(w.x - g0, w.y - g1);
            *(__nv_bfloat162*)&Bs_lo[row][c4 + 2] = __floats2bfloat162_rn(w.z - g2, w.w - g3);
        }
        __syncthreads();

        GEMM_MMA_PHASE(As_hi, As_lo, Bs_hi, Bs_lo)
    }

    const int g = lane >> 2;
    const int t = lane & 3;
    float* dbase = dst + (size_t)head * S_LEN * HD;
#pragma unroll
    for (int mt = 0; mt < 4; mt++) {
#pragma unroll
        for (int nt = 0; nt < 4; nt++) {
            int row = mbase + wy * 64 + mt * 16 + g;
            int col = wx * 32 + nt * 8 + 2 * t;
            float b0 = bias[nbase + col], b1 = bias[nbase + col + 1];
            *(float2*)&dbase[(size_t)row * HD + col] =
                make_float2(acc[mt][nt][0] + b0, acc[mt][nt][1] + b1);
            *(float2*)&dbase[(size_t)(row + 8) * HD + col] =
                make_float2(acc[mt][nt][2] + b0, acc[mt][nt][3] + b1);
        }
    }
}

// ---------------------------------------------------------------------------
// Output projection: out = A @ o_w^T + o_b;  A read from (head, s, d) layout.
// ---------------------------------------------------------------------------
__global__ __launch_bounds__(256, 2) void out_gemm_kernel(
    const float* __restrict__ ow, const float* __restrict__ ob,
    float* __restrict__ out)
{
    __shared__ __nv_bfloat16 As_hi[128][40];
    __shared__ __nv_bfloat16 As_lo[128][40];
    __shared__ __nv_bfloat16 Bs_hi[128][40];
    __shared__ __nv_bfloat16 Bs_lo[128][40];

    const int mbase = blockIdx.x * 128;
    const int nbase = blockIdx.y * 128;
    const int tid  = threadIdx.x;
    const int lane = tid & 31;
    const int warp = tid >> 5;
    const int wy = warp >> 2;
    const int wx = warp & 3;

    const int a_row  = lane & 15;
    const int a_csel = (lane >> 4) << 3;
    const int b_row  = (lane & 7) + ((lane >> 4) & 1) * 8;
    const int b_csel = ((lane >> 3) & 1) * 8;

    float acc[4][4][4];
#pragma unroll
    for (int mt = 0; mt < 4; mt++)
#pragma unroll
        for (int nt = 0; nt < 4; nt++)
#pragma unroll
            for (int e = 0; e < 4; e++) acc[mt][nt][e] = 0.f;

    for (int kt = 0; kt < HID; kt += 32) {
        const float* abase = g_attn + (size_t)(kt >> 7) * (S_LEN * HD) + (kt & 127);
        __syncthreads();
#pragma unroll
        for (int i = 0; i < 4; i++) {
            int j = tid + i * 256;
            int row = j >> 3, c4 = (j & 7) << 2;
            float4 v = *(const float4*)&abase[(size_t)(mbase + row) * HD + c4];
            float h0 = bf16rt(v.x), h1 = bf16rt(v.y), h2 = bf16rt(v.z), h3 = bf16rt(v.w);
            *(__nv_bfloat162*)&As_hi[row][c4]     = __floats2bfloat162_rn(h0, h1);
            *(__nv_bfloat162*)&As_hi[row][c4 + 2] = __floats2bfloat162_rn(h2, h3);
            *(__nv_bfloat162*)&As_lo[row][c4]     = __floats2bfloat162_rn(v.x - h0, v.y - h1);
            *(__nv_bfloat162*)&As_lo[row][c4 + 2] = __floats2bfloat162_rn(v.z - h2, v.w - h3);

            float4 w = *(const float4*)&ow[(size_t)(nbase + row) * HID + kt + c4];
            float g0 = bf16rt(w.x), g1 = bf16rt(w.y), g2 = bf16rt(w.z), g3 = bf16rt(w.w);
            *(__nv_bfloat162*)&Bs_hi[row][c4]     = __floats2bfloat162_rn(g0, g1);
            *(__nv_bfloat162*)&Bs_hi[row][c4 + 2] = __floats2bfloat162_rn(g2, g3);
            *(__nv_bfloat162*)&Bs_lo[row][c4]     = __floats2bfloat162_rn(w.x - g0, w.y - g1);
            *(__nv_bfloat162*)&Bs_lo[row][c4 + 2] = __floats2bfloat162_rn(w.z - g2, w.w - g3);
        }
        __syncthreads();

        GEMM_MMA_PHASE(As_hi, As_lo, Bs_hi, Bs_lo)
    }

    const int g = lane >> 2;
    const int t = lane & 3;
#pragma unroll
    for (int mt = 0; mt < 4; mt++) {
#pragma unroll
        for (int nt = 0; nt < 4; nt++) {
            int row = mbase + wy * 64 + mt * 16 + g;
            int col = wx * 32 + nt * 8 + 2 * t;
            float b0 = ob[nbase + col], b1 = ob[nbase + col + 1];
            *(float2*)&out[(size_t)row * HID + nbase + col] =
                make_float2(acc[mt][nt][0] + b0, acc[mt][nt][1] + b1);
            *(float2*)&out[(size_t)(row + 8) * HID + nbase + col] =
                make_float2(acc[mt][nt][2] + b0, acc[mt][nt][3] + b1);
        }
    }
}

// ===========================================================================
// Attention with split-bf16 MMA (unchanged from passing round-6 kernel).
// ===========================================================================
template<int MODE>   // 0 full, 1 keep j<=i, 2 keep j>i
__device__ __forceinline__ void softmax_update(
    float (&s)[16][4], float (&o)[16][4], float* m, float* l,
    int row0g, int kt, int lane)
{
    const int t = lane & 3;
    float bm0 = -INFINITY, bm1 = -INFINITY;
#pragma unroll
    for (int nt = 0; nt < 16; nt++) {
#pragma unroll
        for (int e = 0; e < 2; e++) {
            int j = kt + nt * 8 + 2 * t + e;
            float v0 = s[nt][e], v1 = s[nt][2 + e];
            if (MODE == 1) { if (j > row0g)      v0 = -INFINITY;
                             if (j > row0g + 8)  v1 = -INFINITY; }
            if (MODE == 2) { if (j <= row0g)     v0 = -INFINITY;
                             if (j <= row0g + 8) v1 = -INFINITY; }
            s[nt][e] = v0; s[nt][2 + e] = v1;
            bm0 = fmaxf(bm0, v0); bm1 = fmaxf(bm1, v1);
        }
    }
    bm0 = fmaxf(bm0, __shfl_xor_sync(0xffffffffu, bm0, 1));
    bm0 = fmaxf(bm0, __shfl_xor_sync(0xffffffffu, bm0, 2));
    bm1 = fmaxf(bm1, __shfl_xor_sync(0xffffffffu, bm1, 1));
    bm1 = fmaxf(bm1, __shfl_xor_sync(0xffffffffu, bm1, 2));
    float mn0 = fmaxf(m[0], bm0), mn1 = fmaxf(m[1], bm1);
    float f0 = __expf(m[0] - mn0), f1 = __expf(m[1] - mn1);
    float rs0 = 0.f, rs1 = 0.f;
#pragma unroll
    for (int nt = 0; nt < 16; nt++) {
#pragma unroll
        for (int e = 0; e < 2; e++) {
            float p0 = __expf(s[nt][e]     - mn0);
            float p1 = __expf(s[nt][2 + e] - mn1);
            s[nt][e] = p0; s[nt][2 + e] = p1;
            rs0 += p0; rs1 += p1;
        }
    }
    rs0 += __shfl_xor_sync(0xffffffffu, rs0, 1);
    rs0 += __shfl_xor_sync(0xffffffffu, rs0, 2);
    rs1 += __shfl_xor_sync(0xffffffffu, rs1, 1);
    rs1 += __shfl_xor_sync(0xffffffffu, rs1, 2);
    l[0] = l[0] * f0 + rs0; m[0] = mn0;
    l[1] = l[1] * f1 + rs1; m[1] = mn1;
#pragma unroll
    for (int nt = 0; nt < 16; nt++) {
        o[nt][0] *= f0; o[nt][1] *= f0;
        o[nt][2] *= f1; o[nt][3] *= f1;
    }
}

#define Q_HI_OFF 0
#define Q_LO_OFF 34816
#define KV_HI_OFF 69632
#define KV_LO_OFF 104448
#define PS_OFF    139264
#define ATT_SMEM  (139264 + 128 * 132 * 4)   // 206848

__global__ __launch_bounds__(256, 1) void attn_kernel()
{
    extern __shared__ char sm[];
    __nv_bfloat16 (*Qh)[136]  = (__nv_bfloat16(*)[136])(sm + Q_HI_OFF);
    __nv_bfloat16 (*Ql)[136]  = (__nv_bfloat16(*)[136])(sm + Q_LO_OFF);
    __nv_bfloat16 (*KVh)[136] = (__nv_bfloat16(*)[136])(sm + KV_HI_OFF);
    __nv_bfloat16 (*KVl)[136] = (__nv_bfloat16(*)[136])(sm + KV_LO_OFF);
    float* Ps = (float*)(sm + PS_OFF);

    const int h  = blockIdx.y;
    const int qt = blockIdx.x;
    const int qbase = qt * 128;
    const int tid  = threadIdx.x;
    const int lane = tid & 31;
    const int warp = tid >> 5;
    const int m0 = warp * 16;
    const int g = lane >> 2;
    const int t = lane & 3;

    const float* __restrict__ Qg = g_q + (size_t)h * S_LEN * HD;
    const float* __restrict__ Kg = g_k + (size_t)h * S_LEN * HD;
    const float* __restrict__ Vg = g_v + (size_t)h * S_LEN * HD;

    const int a_row  = lane & 15;
    const int a_csel = (lane >> 4) << 3;
    const int b_row  = (lane & 7) + ((lane >> 3) & 1) * 8;
    const int b_csel = ((lane >> 4) & 1) * 8;
    const int k_row  = (lane & 7) + ((lane >> 4) & 1) * 8;
    const int k_csel = ((lane >> 3) & 1) * 8;

#pragma unroll
    for (int i = 0; i < 16; i++) {
        int j = tid + i * 256;
        int row = j >> 5, c4 = (j & 31) << 2;
        float4 v = *(const float4*)&Qg[(size_t)(qbase + row) * HD + c4];
        v.x *= ATT_SCALE; v.y *= ATT_SCALE; v.z *= ATT_SCALE; v.w *= ATT_SCALE;
        float h0 = bf16rt(v.x), h1 = bf16rt(v.y), h2 = bf16rt(v.z), h3 = bf16rt(v.w);
        *(__nv_bfloat162*)&Qh[row][c4]     = __floats2bfloat162_rn(h0, h1);
        *(__nv_bfloat162*)&Qh[row][c4 + 2] = __floats2bfloat162_rn(h2, h3);
        *(__nv_bfloat162*)&Ql[row][c4]     = __floats2bfloat162_rn(v.x - h0, v.y - h1);
        *(__nv_bfloat162*)&Ql[row][c4 + 2] = __floats2bfloat162_rn(v.z - h2, v.w - h3);
    }

    float sacc[16][4], oacc[16][4];
    float m[2] = {-INFINITY, -INFINITY}, l[2] = {0.f, 0.f};
    float mM[2], lM[2];
#pragma unroll
    for (int nt = 0; nt < 16; nt++)
#pragma unroll
        for (int e = 0; e < 4; e++) oacc[nt][e] = 0.f;

    const int row0g = qbase + m0 + g;

    auto fill_kv = [&](const float* __restrict__ src, int kt) {
#pragma unroll
        for (int i = 0; i < 16; i++) {
            int j = tid + i * 256;
            int row = j >> 5, c4 = (j & 31) << 2;
            float4 v = *(const float4*)&src[(size_t)(kt + row) * HD + c4];
            float h0 = bf16rt(v.x), h1 = bf16rt(v.y), h2 = bf16rt(v.z), h3 = bf16rt(v.w);
            *(__nv_bfloat162*)&KVh[row][c4]     = __floats2bfloat162_rn(h0, h1);
            *(__nv_bfloat162*)&KVh[row][c4 + 2] = __floats2bfloat162_rn(h2, h3);
            *(__nv_bfloat162*)&KVl[row][c4]     = __floats2bfloat162_rn(v.x - h0, v.y - h1);
            *(__nv_bfloat162*)&KVl[row][c4 + 2] = __floats2bfloat162_rn(v.z - h2, v.w - h3);
        }
    };

    auto pv_accum = [&]() {
#pragma unroll
        for (int kc = 0; kc < 8; kc++) {
            unsigned ph[4], pl[4];
            float* s0 = sacc[2 * kc];
            float* s1 = sacc[2 * kc + 1];
            float h00 = bf16rt(s0[0]), h01 = bf16rt(s0[1]);
            float h02 = bf16rt(s0[2]), h03 = bf16rt(s0[3]);
            float h10 = bf16rt(s1[0]), h11 = bf16rt(s1[1]);
            float h12 = bf16rt(s1[2]), h13 = bf16rt(s1[3]);
            ph[0] = packbf(h00, h01); ph[1] = packbf(h02, h03);
            ph[2] = packbf(h10, h11); ph[3] = packbf(h12, h13);
            pl[0] = packbf(s0[0] - h00, s0[1] - h01);
            pl[1] = packbf(s0[2] - h02, s0[3] - h03);
            pl[2] = packbf(s1[0] - h10, s1[1] - h11);
            pl[3] = packbf(s1[2] - h12, s1[3] - h13);
#pragma unroll
            for (int dp = 0; dp < 8; dp++) {
                int d0 = dp * 16;
                unsigned vh[4], vl[4];
                ldsm4t(&KVh[kc * 16 + b_row][d0 + b_csel], vh);
                ldsm4t(&KVl[kc * 16 + b_row][d0 + b_csel], vl);
                mma_bf(oacc[2 * dp],     ph, vh);
                mma_bf(oacc[2 * dp],     ph, vl);
                mma_bf(oacc[2 * dp],     pl, vh);
                mma_bf(oacc[2 * dp + 1], ph, vh + 2);
                mma_bf(oacc[2 * dp + 1], ph, vl + 2);
                mma_bf(oacc[2 * dp + 1], pl, vh + 2);
            }
        }
    };

    for (int kt = 0; kt < S_LEN; kt += 128) {
        __syncthreads();
        fill_kv(Kg, kt);
        __syncthreads();

#pragma unroll
        for (int nt = 0; nt < 16; nt++)
#pragma unroll
            for (int e = 0; e < 4; e++) sacc[nt][e] = 0.f;
#pragma unroll
        for (int kc = 0; kc < 8; kc++) {
            int k0 = kc * 16;
            unsigned qh[4], ql[4];
            ldsm4(&Qh[m0 + a_row][k0 + a_csel], qh);
            ldsm4(&Ql[m0 + a_row][k0 + a_csel], ql);
#pragma unroll
            for (int ntp = 0; ntp < 8; ntp++) {
                unsigned kh[4], kl[4];
                ldsm4(&KVh[ntp * 16 + k_row][k0 + k_csel], kh);
                ldsm4(&KVl[ntp * 16 + k_row][k0 + k_csel], kl);
                mma_bf(sacc[2 * ntp],     qh, kh);
                mma_bf(sacc[2 * ntp],     qh, kl);
                mma_bf(sacc[2 * ntp],     ql, kh);
                mma_bf(sacc[2 * ntp + 1], qh, kh + 2);
                mma_bf(sacc[2 * ntp + 1], qh, kl + 2);
                mma_bf(sacc[2 * ntp + 1], ql, kh + 2);
            }
        }

        const bool diag = ((kt >> 7) == qt);
        if (diag) {
#pragma unroll
            for (int nt = 0; nt < 16; nt++) {
                int c = nt * 8 + 2 * t;
                *(float2*)&Ps[(m0 + g) * 132 + c]     = make_float2(sacc[nt][0], sacc[nt][1]);
                *(float2*)&Ps[(m0 + 8 + g) * 132 + c] = make_float2(sacc[nt][2], sacc[nt][3]);
            }
        }

        __syncthreads();
        fill_kv(Vg, kt);
        __syncthreads();

        if (!diag) {
            softmax_update<0>(sacc, oacc, m, l, row0g, kt, lane);
            pv_accum();
        } else {
            softmax_update<1>(sacc, oacc, m, l, row0g, kt, lane);
            pv_accum();
            mM[0] = m[0]; lM[0] = l[0]; mM[1] = m[1]; lM[1] = l[1];
            float inv0 = 1.f / (l[0] + 1e-8f), inv1 = 1.f / (l[1] + 1e-8f);
#pragma unroll
            for (int nt = 0; nt < 16; nt++) {
                int c = nt * 8 + 2 * t;
                float2 r0 = *(float2*)&Ps[(m0 + g) * 132 + c];
                float2 r1 = *(float2*)&Ps[(m0 + 8 + g) * 132 + c];
                *(float2*)&Ps[(m0 + g) * 132 + c] =
                    make_float2(oacc[nt][0] * inv0, oacc[nt][1] * inv0);
                *(float2*)&Ps[(m0 + 8 + g) * 132 + c] =
                    make_float2(oacc[nt][2] * inv1, oacc[nt][3] * inv1);
                sacc[nt][0] = r0.x; sacc[nt][1] = r0.y;
                sacc[nt][2] = r1.x; sacc[nt][3] = r1.y;
            }
            softmax_update<2>(sacc, oacc, m, l, row0g, kt, lane);
            pv_accum();
        }
    }

    float a0 = __expf(mM[0] - m[0]), a1 = __expf(mM[1] - m[1]);
    float invU0 = 1.f / (l[0] + 1e-8f), invU1 = 1.f / (l[1] + 1e-8f);
    float den0 = 1.f / (a0 * lM[0] + 3.f * l[0] + 1e-8f);
    float den1 = 1.f / (a1 * lM[1] + 3.f * l[1] + 1e-8f);
    float* Og = g_attn + (size_t)h * S_LEN * HD;
#pragma unroll
    for (int nt = 0; nt < 16; nt++) {
        int c = nt * 8 + 2 * t;
        float2 om0 = *(float2*)&Ps[(m0 + g) * 132 + c];
        float2 om1 = *(float2*)&Ps[(m0 + 8 + g) * 132 + c];
        float2 r0, r1;
        r0.x = (a0 * om0.x + 3.f * oacc[nt][0] * invU0) * den0;
        r0.y = (a0 * om0.y + 3.f * oacc[nt][1] * invU0) * den0;
        r1.x = (a1 * om1.x + 3.f * oacc[nt][2] * invU1) * den1;
        r1.y = (a1 * om1.y + 3.f * oacc[nt][3] * invU1) * den1;
        *(float2*)&Og[(size_t)(qbase + m0 + g) * HD + c]     = r0;
        *(float2*)&Og[(size_t)(qbase + m0 + 8 + g) * HD + c] = r1;
    }
}

extern "C" void kernel_launch(void* const* d_in, const int* in_sizes, int n_in,
                              void* d_out, int out_size)
{
    const float* X  = (const float*)d_in[0];
    const float* qw = (const float*)d_in[1];
    const float* qb = (const float*)d_in[2];
    const float* kw = (const float*)d_in[3];
    const float* kb = (const float*)d_in[4];
    const float* vw = (const float*)d_in[5];
    const float* vb = (const float*)d_in[6];
    const float* ow = (const float*)d_in[7];
    const float* ob = (const float*)d_in[8];
    float* out = (float*)d_out;

    cudaFuncSetAttribute(attn_kernel,
                         cudaFuncAttributeMaxDynamicSharedMemorySize, ATT_SMEM);

    qkv_gemm_kernel<<<dim3(16, 16, 3), 256>>>(X, qw, qb, kw, kb, vw, vb);
    attn_kernel<<<dim3(16, 16), 256, ATT_SMEM>>>();
    out_gemm_kernel<<<dim3(16, 16), 256>>>(ow, ob, out);
}

// round 16
// speedup vs baseline: 1.1249x; 1.0379x over previous
#include <cuda_runtime.h>
#include <cuda_bf16.h>
#include <cstdint>
#include <math.h>

#define S_LEN 2048
#define HID   2048
#define NHEAD 16
#define HD    128
#define NELEM (HID * HID)        // 4.19M, same for all planes here

#define ATT_SCALE 0.08838834764831843f   // 128^-0.5

// ---------------- global split-bf16 planes (device scratch) ----------------
__device__ __nv_bfloat16 gXh[NELEM],  gXl[NELEM];
__device__ __nv_bfloat16 gWqh[NELEM], gWql[NELEM];
__device__ __nv_bfloat16 gWkh[NELEM], gWkl[NELEM];
__device__ __nv_bfloat16 gWvh[NELEM], gWvl[NELEM];
__device__ __nv_bfloat16 gWoh[NELEM], gWol[NELEM];
__device__ __nv_bfloat16 gQh[NELEM],  gQl[NELEM];    // (head, s, d), pre-scaled
__device__ __nv_bfloat16 gKh[NELEM],  gKl[NELEM];
__device__ __nv_bfloat16 gVh[NELEM],  gVl[NELEM];
__device__ __nv_bfloat16 gAh[NELEM],  gAl[NELEM];    // attention output planes
__device__ float gOM[NELEM];                          // masked-output snapshot

// ---------------------------------------------------------------------------
// Helpers
// ---------------------------------------------------------------------------
__device__ __forceinline__ float bf16rt(float x) {
    return __bfloat162float(__float2bfloat16_rn(x));
}
__device__ __forceinline__ unsigned packbf(float a, float b) {
    __nv_bfloat162 t = __floats2bfloat162_rn(a, b);
    return reinterpret_cast<unsigned&>(t);
}
__device__ __forceinline__ void ldsm4(const void* p, unsigned* r) {
    unsigned a = (unsigned)__cvta_generic_to_shared(p);
    asm volatile("ldmatrix.sync.aligned.m8n8.x4.shared.b16 {%0,%1,%2,%3}, [%4];"
                 : "=r"(r[0]), "=r"(r[1]), "=r"(r[2]), "=r"(r[3]) : "r"(a));
}
__device__ __forceinline__ void ldsm4t(const void* p, unsigned* r) {
    unsigned a = (unsigned)__cvta_generic_to_shared(p);
    asm volatile("ldmatrix.sync.aligned.m8n8.x4.trans.shared.b16 {%0,%1,%2,%3}, [%4];"
                 : "=r"(r[0]), "=r"(r[1]), "=r"(r[2]), "=r"(r[3]) : "r"(a));
}
__device__ __forceinline__ void mma_bf(float* c, const unsigned* a, const unsigned* b) {
    asm volatile("mma.sync.aligned.m16n8k16.row.col.f32.bf16.bf16.f32 "
                 "{%0,%1,%2,%3},{%4,%5,%6,%7},{%8,%9},{%0,%1,%2,%3};"
                 : "+f"(c[0]), "+f"(c[1]), "+f"(c[2]), "+f"(c[3])
                 : "r"(a[0]), "r"(a[1]), "r"(a[2]), "r"(a[3]),
                   "r"(b[0]), "r"(b[1]));
}
__device__ __forceinline__ void cp16(unsigned smem_addr, const void* gptr) {
    asm volatile("cp.async.ca.shared.global [%0], [%1], 16;"
                 :: "r"(smem_addr), "l"(gptr) : "memory");
}
#define CP_COMMIT() asm volatile("cp.async.commit_group;" ::: "memory")
#define CP_WAIT1()  asm volatile("cp.async.wait_group 1;" ::: "memory")

// ---------------------------------------------------------------------------
// Pre-convert: fp32 -> hi/lo bf16 planes for X and the 4 weight matrices.
// ---------------------------------------------------------------------------
__global__ __launch_bounds__(256) void preconvert_kernel(
    const float* __restrict__ X,  const float* __restrict__ qw,
    const float* __restrict__ kw, const float* __restrict__ vw,
    const float* __restrict__ ow)
{
    const int a = blockIdx.y;
    const float* src = (a == 0) ? X : (a == 1) ? qw : (a == 2) ? kw
                     : (a == 3) ? vw : ow;
    __nv_bfloat16* dh = (a == 0) ? gXh : (a == 1) ? gWqh : (a == 2) ? gWkh
                      : (a == 3) ? gWvh : gWoh;
    __nv_bfloat16* dl = (a == 0) ? gXl : (a == 1) ? gWql : (a == 2) ? gWkl
                      : (a == 3) ? gWvl : gWol;

    size_t i = ((size_t)blockIdx.x * 256 + threadIdx.x) * 4;
    float4 v = *(const float4*)&src[i];
    float h0 = bf16rt(v.x), h1 = bf16rt(v.y), h2 = bf16rt(v.z), h3 = bf16rt(v.w);
    *(__nv_bfloat162*)&dh[i]     = __floats2bfloat162_rn(h0, h1);
    *(__nv_bfloat162*)&dh[i + 2] = __floats2bfloat162_rn(h2, h3);
    *(__nv_bfloat162*)&dl[i]     = __floats2bfloat162_rn(v.x - h0, v.y - h1);
    *(__nv_bfloat162*)&dl[i + 2] = __floats2bfloat162_rn(v.z - h2, v.w - h3);
}

// ===========================================================================
// Frag-reuse MMA phase (from R14; every fragment ldmatrix'd once per k16).
// ===========================================================================
#define GEMM_MMA_PHASE(ASH, ASL, BSH, BSL)                                     \
    _Pragma("unroll")                                                          \
    for (int k16 = 0; k16 < 2; k16++) {                                        \
        int k0 = k16 * 16;                                                     \
        unsigned bh[2][4], bl[2][4];                                           \
        _Pragma("unroll")                                                      \
        for (int ntp = 0; ntp < 2; ntp++) {                                    \
            ldsm4(&BSH[wx * 32 + ntp * 16 + b_row][k0 + b_csel], bh[ntp]);     \
            ldsm4(&BSL[wx * 32 + ntp * 16 + b_row][k0 + b_csel], bl[ntp]);     \
        }                                                                      \
        _Pragma("unroll")                                                      \
        for (int mt = 0; mt < 4; mt++) {                                       \
            unsigned ah[4], al[4];                                             \
            ldsm4(&ASH[wy * 64 + mt * 16 + a_row][k0 + a_csel], ah);           \
            ldsm4(&ASL[wy * 64 + mt * 16 + a_row][k0 + a_csel], al);           \
            mma_bf(acc[mt][0], ah, bh[0]);                                     \
            mma_bf(acc[mt][1], ah, bh[0] + 2);                                 \
            mma_bf(acc[mt][2], ah, bh[1]);                                     \
            mma_bf(acc[mt][3], ah, bh[1] + 2);                                 \
            mma_bf(acc[mt][0], ah, bl[0]);                                     \
            mma_bf(acc[mt][1], ah, bl[0] + 2);                                 \
            mma_bf(acc[mt][2], ah, bl[1]);                                     \
            mma_bf(acc[mt][3], ah, bl[1] + 2);                                 \
            mma_bf(acc[mt][0], al, bh[0]);                                     \
            mma_bf(acc[mt][1], al, bh[0] + 2);                                 \
            mma_bf(acc[mt][2], al, bh[1]);                                     \
            mma_bf(acc[mt][3], al, bh[1] + 2);                                 \
        }                                                                      \
    }

// GEMM stage layout (bytes): Ah 0, Al 10240, Bh 20480, Bl 30720; stage 40960.
#define G_STG 40960
#define G_SMEM (2 * G_STG)
#define G_NCH (HID / 32)   // 64 chunks

// ---------------------------------------------------------------------------
// QKV projection: pure-bf16 cp.async double-buffered GEMM.
// Writes q/k/v as split-bf16 planes in (head, s, d); q pre-scaled.
// ---------------------------------------------------------------------------
__global__ __launch_bounds__(256, 2) void qkv_gemm_kernel(
    const float* __restrict__ qb, const float* __restrict__ kb,
    const float* __restrict__ vb)
{
    extern __shared__ char smem[];
    const unsigned sbase = (unsigned)__cvta_generic_to_shared(smem);

    const int z = blockIdx.z;
    const __nv_bfloat16* Wh = (z == 0) ? gWqh : (z == 1) ? gWkh : gWvh;
    const __nv_bfloat16* Wl = (z == 0) ? gWql : (z == 1) ? gWkl : gWvl;
    const float* bias = (z == 0) ? qb : (z == 1) ? kb : vb;
    __nv_bfloat16* dsth = (z == 0) ? gQh : (z == 1) ? gKh : gVh;
    __nv_bfloat16* dstl = (z == 0) ? gQl : (z == 1) ? gKl : gVl;
    const float outscale = (z == 0) ? ATT_SCALE : 1.0f;

    const int mbase = blockIdx.x * 128;
    const int head  = blockIdx.y;
    const int nbase = head * 128;
    const int tid  = threadIdx.x;
    const int lane = tid & 31;
    const int warp = tid >> 5;
    const int wy = warp >> 2;
    const int wx = warp & 3;

    const int a_row  = lane & 15;
    const int a_csel = (lane >> 4) << 3;
    const int b_row  = (lane & 7) + ((lane >> 4) & 1) * 8;
    const int b_csel = ((lane >> 3) & 1) * 8;

    auto issue = [&](int ch, int stg) {
        const int kt = ch * 32;
        unsigned sb = sbase + stg * G_STG;
#pragma unroll
        for (int i = 0; i < 2; i++) {
            int c = tid + i * 256;              // 0..511
            int row = c >> 2, q = c & 3;
            int cc = q * 8;
            unsigned d = sb + row * 80 + q * 16;
            size_t ao = (size_t)(mbase + row) * HID + kt + cc;
            size_t bo = (size_t)(nbase + row) * HID + kt + cc;
            cp16(d,         gXh + ao);
            cp16(d + 10240, gXl + ao);
            cp16(d + 20480, Wh + bo);
            cp16(d + 30720, Wl + bo);
        }
    };

    float acc[4][4][4];
#pragma unroll
    for (int mt = 0; mt < 4; mt++)
#pragma unroll
        for (int nt = 0; nt < 4; nt++)
#pragma unroll
            for (int e = 0; e < 4; e++) acc[mt][nt][e] = 0.f;

    issue(0, 0); CP_COMMIT();
    issue(1, 1); CP_COMMIT();

    for (int ch = 0; ch < G_NCH; ch++) {
        CP_WAIT1();
        __syncthreads();
        const int p = ch & 1;
        const __nv_bfloat16 (*ASH)[40] = (const __nv_bfloat16(*)[40])(smem + p * G_STG);
        const __nv_bfloat16 (*ASL)[40] = (const __nv_bfloat16(*)[40])(smem + p * G_STG + 10240);
        const __nv_bfloat16 (*BSH)[40] = (const __nv_bfloat16(*)[40])(smem + p * G_STG + 20480);
        const __nv_bfloat16 (*BSL)[40] = (const __nv_bfloat16(*)[40])(smem + p * G_STG + 30720);
        GEMM_MMA_PHASE(ASH, ASL, BSH, BSL)
        __syncthreads();
        if (ch + 2 < G_NCH) issue(ch + 2, p);
        CP_COMMIT();
    }

    const int g = lane >> 2;
    const int t = lane & 3;
    const size_t hoff = (size_t)head * S_LEN * HD;
#pragma unroll
    for (int mt = 0; mt < 4; mt++) {
#pragma unroll
        for (int nt = 0; nt < 4; nt++) {
            int row = mbase + wy * 64 + mt * 16 + g;
            int col = wx * 32 + nt * 8 + 2 * t;
            float b0 = bias[nbase + col], b1 = bias[nbase + col + 1];
#pragma unroll
            for (int rr = 0; rr < 2; rr++) {
                float v0 = (acc[mt][nt][2 * rr]     + b0) * outscale;
                float v1 = (acc[mt][nt][2 * rr + 1] + b1) * outscale;
                float h0 = bf16rt(v0), h1 = bf16rt(v1);
                size_t idx = hoff + (size_t)(row + rr * 8) * HD + col;
                *(__nv_bfloat162*)&dsth[idx] = __floats2bfloat162_rn(h0, h1);
                *(__nv_bfloat162*)&dstl[idx] = __floats2bfloat162_rn(v0 - h0, v1 - h1);
            }
        }
    }
}

// ---------------------------------------------------------------------------
// Output projection: A from gAh/gAl ((head,s,d) gather), B from gWoh/gWol.
// ---------------------------------------------------------------------------
__global__ __launch_bounds__(256, 2) void out_gemm_kernel(
    const float* __restrict__ ob, float* __restrict__ out)
{
    extern __shared__ char smem[];
    const unsigned sbase = (unsigned)__cvta_generic_to_shared(smem);

    const int mbase = blockIdx.x * 128;
    const int nbase = blockIdx.y * 128;
    const int tid  = threadIdx.x;
    const int lane = tid & 31;
    const int warp = tid >> 5;
    const int wy = warp >> 2;
    const int wx = warp & 3;

    const int a_row  = lane & 15;
    const int a_csel = (lane >> 4) << 3;
    const int b_row  = (lane & 7) + ((lane >> 4) & 1) * 8;
    const int b_csel = ((lane >> 3) & 1) * 8;

    auto issue = [&](int ch, int stg) {
        const int kt = ch * 32;
        unsigned sb = sbase + stg * G_STG;
        const size_t aplane = (size_t)(kt >> 7) * (S_LEN * HD) + (kt & 127);
#pragma unroll
        for (int i = 0; i < 2; i++) {
            int c = tid + i * 256;
            int row = c >> 2, q = c & 3;
            int cc = q * 8;
            unsigned d = sb + row * 80 + q * 16;
            size_t ao = aplane + (size_t)(mbase + row) * HD + cc;
            size_t bo = (size_t)(nbase + row) * HID + kt + cc;
            cp16(d,         gAh + ao);
            cp16(d + 10240, gAl + ao);
            cp16(d + 20480, gWoh + bo);
            cp16(d + 30720, gWol + bo);
        }
    };

    float acc[4][4][4];
#pragma unroll
    for (int mt = 0; mt < 4; mt++)
#pragma unroll
        for (int nt = 0; nt < 4; nt++)
#pragma unroll
            for (int e = 0; e < 4; e++) acc[mt][nt][e] = 0.f;

    issue(0, 0); CP_COMMIT();
    issue(1, 1); CP_COMMIT();

    for (int ch = 0; ch < G_NCH; ch++) {
        CP_WAIT1();
        __syncthreads();
        const int p = ch & 1;
        const __nv_bfloat16 (*ASH)[40] = (const __nv_bfloat16(*)[40])(smem + p * G_STG);
        const __nv_bfloat16 (*ASL)[40] = (const __nv_bfloat16(*)[40])(smem + p * G_STG + 10240);
        const __nv_bfloat16 (*BSH)[40] = (const __nv_bfloat16(*)[40])(smem + p * G_STG + 20480);
        const __nv_bfloat16 (*BSL)[40] = (const __nv_bfloat16(*)[40])(smem + p * G_STG + 30720);
        GEMM_MMA_PHASE(ASH, ASL, BSH, BSL)
        __syncthreads();
        if (ch + 2 < G_NCH) issue(ch + 2, p);
        CP_COMMIT();
    }

    const int g = lane >> 2;
    const int t = lane & 3;
#pragma unroll
    for (int mt = 0; mt < 4; mt++) {
#pragma unroll
        for (int nt = 0; nt < 4; nt++) {
            int row = mbase + wy * 64 + mt * 16 + g;
            int col = wx * 32 + nt * 8 + 2 * t;
            float b0 = ob[nbase + col], b1 = ob[nbase + col + 1];
            *(float2*)&out[(size_t)row * HID + nbase + col] =
                make_float2(acc[mt][nt][0] + b0, acc[mt][nt][1] + b1);
            *(float2*)&out[(size_t)(row + 8) * HID + nbase + col] =
                make_float2(acc[mt][nt][2] + b0, acc[mt][nt][3] + b1);
        }
    }
}

// ===========================================================================
// Attention: cp.async pipelined, split-bf16 inputs, separate K/V buffers.
// Diag recomputes S from the resident K tile; oM snapshot via gOM.
// ===========================================================================
template<int MODE>   // 0 full, 1 keep j<=i, 2 keep j>i
__device__ __forceinline__ void softmax_update(
    float (&s)[16][4], float (&o)[16][4], float* m, float* l,
    int row0g, int kt, int lane)
{
    const int t = lane & 3;
    float bm0 = -INFINITY, bm1 = -INFINITY;
#pragma unroll
    for (int nt = 0; nt < 16; nt++) {
#pragma unroll
        for (int e = 0; e < 2; e++) {
            int j = kt + nt * 8 + 2 * t + e;
            float v0 = s[nt][e], v1 = s[nt][2 + e];
            if (MODE == 1) { if (j > row0g)      v0 = -INFINITY;
                             if (j > row0g + 8)  v1 = -INFINITY; }
            if (MODE == 2) { if (j <= row0g)     v0 = -INFINITY;
                             if (j <= row0g + 8) v1 = -INFINITY; }
            s[nt][e] = v0; s[nt][2 + e] = v1;
            bm0 = fmaxf(bm0, v0); bm1 = fmaxf(bm1, v1);
        }
    }
    bm0 = fmaxf(bm0, __shfl_xor_sync(0xffffffffu, bm0, 1));
    bm0 = fmaxf(bm0, __shfl_xor_sync(0xffffffffu, bm0, 2));
    bm1 = fmaxf(bm1, __shfl_xor_sync(0xffffffffu, bm1, 1));
    bm1 = fmaxf(bm1, __shfl_xor_sync(0xffffffffu, bm1, 2));
    float mn0 = fmaxf(m[0], bm0), mn1 = fmaxf(m[1], bm1);
    float f0 = __expf(m[0] - mn0), f1 = __expf(m[1] - mn1);
    float rs0 = 0.f, rs1 = 0.f;
#pragma unroll
    for (int nt = 0; nt < 16; nt++) {
#pragma unroll
        for (int e = 0; e < 2; e++) {
            float p0 = __expf(s[nt][e]     - mn0);
            float p1 = __expf(s[nt][2 + e] - mn1);
            s[nt][e] = p0; s[nt][2 + e] = p1;
            rs0 += p0; rs1 += p1;
        }
    }
    rs0 += __shfl_xor_sync(0xffffffffu, rs0, 1);
    rs0 += __shfl_xor_sync(0xffffffffu, rs0, 2);
    rs1 += __shfl_xor_sync(0xffffffffu, rs1, 1);
    rs1 += __shfl_xor_sync(0xffffffffu, rs1, 2);
    l[0] = l[0] * f0 + rs0; m[0] = mn0;
    l[1] = l[1] * f1 + rs1; m[1] = mn1;
#pragma unroll
    for (int nt = 0; nt < 16; nt++) {
        o[nt][0] *= f0; o[nt][1] *= f0;
        o[nt][2] *= f1; o[nt][3] *= f1;
    }
}

// attn smem layout (bytes), stride 136 bf16 per row (272B):
#define AQ_H 0
#define AQ_L 34816
#define AK_H 69632
#define AK_L 104448
#define AV_H 139264
#define AV_L 174080
#define ATT_SMEM 208896

__global__ __launch_bounds__(256, 1) void attn_kernel()
{
    extern __shared__ char sm[];
    const unsigned sbase = (unsigned)__cvta_generic_to_shared(sm);
    __nv_bfloat16 (*Qh)[136] = (__nv_bfloat16(*)[136])(sm + AQ_H);
    __nv_bfloat16 (*Ql)[136] = (__nv_bfloat16(*)[136])(sm + AQ_L);
    __nv_bfloat16 (*Kh)[136] = (__nv_bfloat16(*)[136])(sm + AK_H);
    __nv_bfloat16 (*Kl)[136] = (__nv_bfloat16(*)[136])(sm + AK_L);
    __nv_bfloat16 (*Vh)[136] = (__nv_bfloat16(*)[136])(sm + AV_H);
    __nv_bfloat16 (*Vl)[136] = (__nv_bfloat16(*)[136])(sm + AV_L);

    const int h  = blockIdx.y;
    const int qt = blockIdx.x;
    const int qbase = qt * 128;
    const int tid  = threadIdx.x;
    const int lane = tid & 31;
    const int warp = tid >> 5;
    const int m0 = warp * 16;
    const int g = lane >> 2;
    const int t = lane & 3;
    const size_t hoff = (size_t)h * S_LEN * HD;

    const int a_row  = lane & 15;
    const int a_csel = (lane >> 4) << 3;
    const int b_row  = (lane & 7) + ((lane >> 3) & 1) * 8;
    const int b_csel = ((lane >> 4) & 1) * 8;
    const int k_row  = (lane & 7) + ((lane >> 4) & 1) * 8;
    const int k_csel = ((lane >> 3) & 1) * 8;

    // cp.async one 128x128 tile (hi+lo planes) into smem at dstoff/+34816.
    auto cp_tile = [&](unsigned dstoff, const __nv_bfloat16* sh,
                       const __nv_bfloat16* sl, int kt) {
#pragma unroll
        for (int i = 0; i < 8; i++) {
            int c = tid + i * 256;           // 0..2047
            int row = c >> 4, q = c & 15;
            unsigned d = sbase + dstoff + row * 272 + q * 16;
            size_t so = (size_t)(kt + row) * HD + q * 8;
            cp16(d,         sh + so);
            cp16(d + 34816, sl + so);
        }
    };

    float sacc[16][4], oacc[16][4];
    float m[2] = {-INFINITY, -INFINITY}, l[2] = {0.f, 0.f};
    float mM[2], lM[2];
#pragma unroll
    for (int nt = 0; nt < 16; nt++)
#pragma unroll
        for (int e = 0; e < 4; e++) oacc[nt][e] = 0.f;

    const int row0g = qbase + m0 + g;

    auto compute_s = [&]() {
#pragma unroll
        for (int nt = 0; nt < 16; nt++)
#pragma unroll
            for (int e = 0; e < 4; e++) sacc[nt][e] = 0.f;
#pragma unroll
        for (int kc = 0; kc < 8; kc++) {
            int k0 = kc * 16;
            unsigned qh[4], ql[4];
            ldsm4(&Qh[m0 + a_row][k0 + a_csel], qh);
            ldsm4(&Ql[m0 + a_row][k0 + a_csel], ql);
#pragma unroll
            for (int ntp = 0; ntp < 8; ntp++) {
                unsigned kh[4], kl[4];
                ldsm4(&Kh[ntp * 16 + k_row][k0 + k_csel], kh);
                ldsm4(&Kl[ntp * 16 + k_row][k0 + k_csel], kl);
                mma_bf(sacc[2 * ntp],     qh, kh);
                mma_bf(sacc[2 * ntp],     qh, kl);
                mma_bf(sacc[2 * ntp],     ql, kh);
                mma_bf(sacc[2 * ntp + 1], qh, kh + 2);
                mma_bf(sacc[2 * ntp + 1], qh, kl + 2);
                mma_bf(sacc[2 * ntp + 1], ql, kh + 2);
            }
        }
    };

    auto pv_accum = [&]() {
#pragma unroll
        for (int kc = 0; kc < 8; kc++) {
            unsigned ph[4], pl[4];
            float* s0 = sacc[2 * kc];
            float* s1 = sacc[2 * kc + 1];
            float h00 = bf16rt(s0[0]), h01 = bf16rt(s0[1]);
            float h02 = bf16rt(s0[2]), h03 = bf16rt(s0[3]);
            float h10 = bf16rt(s1[0]), h11 = bf16rt(s1[1]);
            float h12 = bf16rt(s1[2]), h13 = bf16rt(s1[3]);
            ph[0] = packbf(h00, h01); ph[1] = packbf(h02, h03);
            ph[2] = packbf(h10, h11); ph[3] = packbf(h12, h13);
            pl[0] = packbf(s0[0] - h00, s0[1] - h01);
            pl[1] = packbf(s0[2] - h02, s0[3] - h03);
            pl[2] = packbf(s1[0] - h10, s1[1] - h11);
            pl[3] = packbf(s1[2] - h12, s1[3] - h13);
#pragma unroll
            for (int dp = 0; dp < 8; dp++) {
                int d0 = dp * 16;
                unsigned vh[4], vl[4];
                ldsm4t(&Vh[kc * 16 + b_row][d0 + b_csel], vh);
                ldsm4t(&Vl[kc * 16 + b_row][d0 + b_csel], vl);
                mma_bf(oacc[2 * dp],     ph, vh);
                mma_bf(oacc[2 * dp],     ph, vl);
                mma_bf(oacc[2 * dp],     pl, vh);
                mma_bf(oacc[2 * dp + 1], ph, vh + 2);
                mma_bf(oacc[2 * dp + 1], ph, vl + 2);
                mma_bf(oacc[2 * dp + 1], pl, vh + 2);
            }
        }
    };

    // Prologue: group0 = {Q, K0}, group1 = {V0}.
    cp_tile(AQ_H, gQh + hoff, gQl + hoff, qbase);
    cp_tile(AK_H, gKh + hoff, gKl + hoff, 0);
    CP_COMMIT();
    cp_tile(AV_H, gVh + hoff, gVl + hoff, 0);
    CP_COMMIT();

    for (int it = 0; it < 16; it++) {
        const int kt = it * 128;
        const bool diag = (it == qt);

        CP_WAIT1();                 // K(it) (and Q on it=0) arrived
        __syncthreads();
        compute_s();
        __syncthreads();            // all warps done reading K
        if (!diag && it + 1 < 16)
            cp_tile(AK_H, gKh + hoff, gKl + hoff, kt + 128);
        CP_COMMIT();                // (empty on diag / last)

        CP_WAIT1();                 // V(it) arrived
        __syncthreads();
        if (!diag) {
            softmax_update<0>(sacc, oacc, m, l, row0g, kt, lane);
            pv_accum();
        } else {
            softmax_update<1>(sacc, oacc, m, l, row0g, kt, lane);
            pv_accum();
            mM[0] = m[0]; lM[0] = l[0]; mM[1] = m[1]; lM[1] = l[1];
            float inv0 = 1.f / (l[0] + 1e-8f), inv1 = 1.f / (l[1] + 1e-8f);
#pragma unroll
            for (int nt = 0; nt < 16; nt++) {
                int c = nt * 8 + 2 * t;
                *(float2*)&gOM[hoff + (size_t)(qbase + m0 + g) * HD + c] =
                    make_float2(oacc[nt][0] * inv0, oacc[nt][1] * inv0);
                *(float2*)&gOM[hoff + (size_t)(qbase + m0 + 8 + g) * HD + c] =
                    make_float2(oacc[nt][2] * inv1, oacc[nt][3] * inv1);
            }
            compute_s();            // K tile still resident
            softmax_update<2>(sacc, oacc, m, l, row0g, kt, lane);
            pv_accum();
        }
        __syncthreads();            // done reading V (and K on diag)
        if (diag && it + 1 < 16) {
            cp_tile(AK_H, gKh + hoff, gKl + hoff, kt + 128);
            CP_COMMIT();
        }
        if (it + 1 < 16)
            cp_tile(AV_H, gVh + hoff, gVl + hoff, kt + 128);
        CP_COMMIT();
    }

    // Combine: final = (a*oM + 3*oU_norm) / (a*lM + 3*lU + 1e-8); write planes.
    float a0 = __expf(mM[0] - m[0]), a1 = __expf(mM[1] - m[1]);
    float invU0 = 1.f / (l[0] + 1e-8f), invU1 = 1.f / (l[1] + 1e-8f);
    float den0 = 1.f / (a0 * lM[0] + 3.f * l[0] + 1e-8f);
    float den1 = 1.f / (a1 * lM[1] + 3.f * l[1] + 1e-8f);
#pragma unroll
    for (int nt = 0; nt < 16; nt++) {
        int c = nt * 8 + 2 * t;
        size_t i0 = hoff + (size_t)(qbase + m0 + g) * HD + c;
        size_t i1 = hoff + (size_t)(qbase + m0 + 8 + g) * HD + c;
        float2 om0 = *(float2*)&gOM[i0];
        float2 om1 = *(float2*)&gOM[i1];
        float r0x = (a0 * om0.x + 3.f * oacc[nt][0] * invU0) * den0;
        float r0y = (a0 * om0.y + 3.f * oacc[nt][1] * invU0) * den0;
        float r1x = (a1 * om1.x + 3.f * oacc[nt][2] * invU1) * den1;
        float r1y = (a1 * om1.y + 3.f * oacc[nt][3] * invU1) * den1;
        float h0x = bf16rt(r0x), h0y = bf16rt(r0y);
        float h1x = bf16rt(r1x), h1y = bf16rt(r1y);
        *(__nv_bfloat162*)&gAh[i0] = __floats2bfloat162_rn(h0x, h0y);
        *(__nv_bfloat162*)&gAl[i0] = __floats2bfloat162_rn(r0x - h0x, r0y - h0y);
        *(__nv_bfloat162*)&gAh[i1] = __floats2bfloat162_rn(h1x, h1y);
        *(__nv_bfloat162*)&gAl[i1] = __floats2bfloat162_rn(r1x - h1x, r1y - h1y);
    }
}

extern "C" void kernel_launch(void* const* d_in, const int* in_sizes, int n_in,
                              void* d_out, int out_size)
{
    const float* X  = (const float*)d_in[0];
    const float* qw = (const float*)d_in[1];
    const float* qb = (const float*)d_in[2];
    const float* kw = (const float*)d_in[3];
    const float* kb = (const float*)d_in[4];
    const float* vw = (const float*)d_in[5];
    const float* vb = (const float*)d_in[6];
    const float* ow = (const float*)d_in[7];
    const float* ob = (const float*)d_in[8];
    float* out = (float*)d_out;

    cudaFuncSetAttribute(qkv_gemm_kernel,
                         cudaFuncAttributeMaxDynamicSharedMemorySize, G_SMEM);
    cudaFuncSetAttribute(out_gemm_kernel,
                         cudaFuncAttributeMaxDynamicSharedMemorySize, G_SMEM);
    cudaFuncSetAttribute(attn_kernel,
                         cudaFuncAttributeMaxDynamicSharedMemorySize, ATT_SMEM);

    preconvert_kernel<<<dim3(NELEM / 1024, 5), 256>>>(X, qw, kw, vw, ow);
    qkv_gemm_kernel<<<dim3(16, 16, 3), 256, G_SMEM>>>(qb, kb, vb);
    attn_kernel<<<dim3(16, 16), 256, ATT_SMEM>>>();
    out_gemm_kernel<<<dim3(16, 16), 256, G_SMEM>>>(ob, out);
}